// round 6
// baseline (speedup 1.0000x reference)
#include <cuda_runtime.h>
#include <cuda_fp16.h>
#include <stdint.h>

#define N_NODES 50000
#define N_EDGES 1600000
#define F_IN 128
#define F_H  64
#define F_OUT 32

// ---------------- device scratch (no allocations allowed) ----------------
__device__ int     g_is64;
__device__ int     g_eisel;
__device__ int     g_row[N_EDGES];
__device__ int     g_col[N_EDGES];
__device__ int     g_cnt[N_NODES];
__device__ int     g_cur[N_NODES];
__device__ int     g_off[N_NODES + 1];
__device__ float   g_dinv[N_NODES];
__device__ int2    g_csr[N_EDGES];            // {row, norm bits}
__device__ __half2 g_h0[N_NODES * (F_H / 2)]; // x @ W1   (fp16 pairs)
__device__ __half2 g_h [N_NODES * (F_H / 2)]; // relu(A_hat h0 + b1)
__device__ float2  g_g [N_NODES * (F_H / 2)]; // A_hat h  (fp32)

// ---------------- zero + probe (fused) ----------------
// int64 edge values < 50000 => every odd 32-bit word is 0; float x never all-zero.
__global__ void k_zero_probe(const int* __restrict__ c0, const int* __restrict__ c1,
                             int tie, int host_eisel, int n) {
    int i = blockIdx.x * blockDim.x + threadIdx.x;
    if (i < n) { g_cnt[i] = 0; g_cur[i] = 0; }
    if (i == 0) {
        if (tie) {
            int any0 = 0;
            for (int k = 1; k < 2048; k += 2) any0 |= c0[k];
            g_eisel = (any0 == 0) ? 0 : 1;
            g_is64 = 1;
        } else {
            g_eisel = host_eisel;
            const int* w = host_eisel ? c1 : c0;
            int any = 0;
            for (int k = 1; k < 2048; k += 2) any |= w[k];
            g_is64 = (any == 0) ? 1 : 0;
        }
    }
}

// ---------------- decode + degree count (fused) ----------------
__global__ void k_decode_count(const void* __restrict__ c0, const void* __restrict__ c1,
                               int e, int n) {
    int i = blockIdx.x * blockDim.x + threadIdx.x;
    if (i >= e) return;
    const void* p = g_eisel ? c1 : c0;
    int r, c;
    if (g_is64) {
        const long long* q = (const long long*)p;
        r = (int)q[i];
        c = (int)q[e + i];
    } else {
        const int* q = (const int*)p;
        r = q[i];
        c = q[e + i];
    }
    if ((unsigned)r >= (unsigned)n) r = 0;
    if ((unsigned)c >= (unsigned)n) c = 0;
    g_row[i] = r;
    g_col[i] = c;
    atomicAdd(&g_cnt[c], 1);
}

// ---------------- scan + dinv (fused single block) ----------------
__global__ void k_scan(int n) {
    __shared__ int s[1024];
    int t = threadIdx.x;
    int ch = (n + 1023) >> 10;
    int start = t * ch;
    int sum = 0;
    for (int i = 0; i < ch; i++) {
        int idx = start + i;
        if (idx < n) sum += g_cnt[idx];
    }
    s[t] = sum;
    __syncthreads();
    for (int d = 1; d < 1024; d <<= 1) {
        int v = (t >= d) ? s[t - d] : 0;
        __syncthreads();
        s[t] += v;
        __syncthreads();
    }
    int run = (t == 0) ? 0 : s[t - 1];
    for (int i = 0; i < ch; i++) {
        int idx = start + i;
        if (idx < n) {
            g_off[idx] = run;
            int cnt = g_cnt[idx];
            run += cnt;
            g_dinv[idx] = rsqrtf((float)cnt + 1.0f);
        }
    }
    if (t == 1023) g_off[n] = run;
}

// ---------------- fill packed CSR ----------------
__global__ void k_fill(int e) {
    int i = blockIdx.x * blockDim.x + threadIdx.x;
    if (i < e) {
        int row = g_row[i];
        int col = g_col[i];
        int pos = g_off[col] + atomicAdd(&g_cur[col], 1);
        float nrm = g_dinv[row] * g_dinv[col];
        g_csr[pos] = make_int2(row, __float_as_int(nrm));
    }
}

// ---------------- h0 = x @ W1 (128 -> 64), output fp16 ----------------
__global__ void k_gemm1(const float* __restrict__ c0, const float* __restrict__ c1,
                        const float* __restrict__ W1, int n) {
    __shared__ float Ws[F_IN * F_H];      // 32 KB
    __shared__ float xs[4][F_IN];
    const float* x = g_eisel ? c0 : c1;
    int tx = threadIdx.x;                  // 0..63 : out feature
    int ty = threadIdx.y;                  // 0..3  : node in block
    int tid = ty * 64 + tx;
    for (int i = tid; i < F_IN * F_H; i += 256) Ws[i] = W1[i];
    int node = blockIdx.x * 4 + ty;
    for (int i = tx; i < F_IN; i += 64)
        xs[ty][i] = (node < n) ? x[node * F_IN + i] : 0.0f;
    __syncthreads();
    if (node < n) {
        float acc = 0.0f;
#pragma unroll
        for (int k = 0; k < F_IN; k++)
            acc = fmaf(xs[ty][k], Ws[k * F_H + tx], acc);
        ((__half*)g_h0)[node * F_H + tx] = __float2half_rn(acc);
    }
}

// ---------------- warp-per-node gathers (fp16 features, 128B/edge) ----------------
// h = relu(A_hat h0 + b1)
__global__ void k_gather1(const float* __restrict__ bias, int n) {
    int warp = (blockIdx.x * blockDim.x + threadIdx.x) >> 5;
    int lane = threadIdx.x & 31;
    if (warp >= n) return;
    float di = g_dinv[warp];
    float sl = di * di;
    float2 fs = __half22float2(g_h0[warp * 32 + lane]);
    float a0 = fs.x * sl;
    float a1 = fs.y * sl;
    int s = g_off[warp], e = g_off[warp + 1];
#pragma unroll 4
    for (int j = s; j < e; j++) {
        int2 m = __ldg(&g_csr[j]);
        float w = __int_as_float(m.y);
        float2 f = __half22float2(__ldg(&g_h0[m.x * 32 + lane]));
        a0 = fmaf(f.x, w, a0);
        a1 = fmaf(f.y, w, a1);
    }
    float2 b = ((const float2*)bias)[lane];
    a0 = fmaxf(a0 + b.x, 0.0f);
    a1 = fmaxf(a1 + b.y, 0.0f);
    g_h[warp * 32 + lane] = __floats2half2_rn(a0, a1);
}

// g = A_hat h   (fp32 out)
__global__ void k_gather2(int n) {
    int warp = (blockIdx.x * blockDim.x + threadIdx.x) >> 5;
    int lane = threadIdx.x & 31;
    if (warp >= n) return;
    float di = g_dinv[warp];
    float sl = di * di;
    float2 fs = __half22float2(g_h[warp * 32 + lane]);
    float a0 = fs.x * sl;
    float a1 = fs.y * sl;
    int s = g_off[warp], e = g_off[warp + 1];
#pragma unroll 4
    for (int j = s; j < e; j++) {
        int2 m = __ldg(&g_csr[j]);
        float w = __int_as_float(m.y);
        float2 f = __half22float2(__ldg(&g_h[m.x * 32 + lane]));
        a0 = fmaf(f.x, w, a0);
        a1 = fmaf(f.y, w, a1);
    }
    g_g[warp * 32 + lane] = make_float2(a0, a1);
}

// ---------------- output heads ----------------
__global__ void k_out(const float* __restrict__ Wmu, const float* __restrict__ bmu,
                      const float* __restrict__ Wls, const float* __restrict__ bls,
                      float* __restrict__ out, int n) {
    __shared__ float Wm[F_H * F_OUT];
    __shared__ float Wl[F_H * F_OUT];
    __shared__ float gs[8][F_H];
    int tx = threadIdx.x;                 // 0..31 : out feature
    int ty = threadIdx.y;                 // 0..7  : node in block
    int tid = ty * 32 + tx;
    for (int i = tid; i < F_H * F_OUT; i += 256) { Wm[i] = Wmu[i]; Wl[i] = Wls[i]; }
    int node = blockIdx.x * 8 + ty;
    const float* gg = (const float*)g_g;
    for (int i = tx; i < F_H; i += 32)
        gs[ty][i] = (node < n) ? gg[node * F_H + i] : 0.0f;
    __syncthreads();
    if (node < n) {
        float am = 0.0f, al = 0.0f;
#pragma unroll
        for (int k = 0; k < F_H; k++) {
            float v = gs[ty][k];
            am = fmaf(v, Wm[k * F_OUT + tx], am);
            al = fmaf(v, Wl[k * F_OUT + tx], al);
        }
        out[node * F_OUT + tx]             = am + bmu[tx];
        out[n * F_OUT + node * F_OUT + tx] = al + bls[tx];
    }
}

// ---------------- launch ----------------
extern "C" void kernel_launch(void* const* d_in, const int* in_sizes, int n_in,
                              void* d_out, int out_size) {
    int n = out_size / (2 * F_OUT);

    long long best1 = -1, best2 = -1; int i1 = -1, i2 = -1;
    for (int i = 0; i < n_in; i++) {
        long long s = in_sizes[i];
        if (s > best1) { best2 = best1; i2 = i1; best1 = s; i1 = i; }
        else if (s > best2) { best2 = s; i2 = i; }
    }
    int tie = (best1 == best2);

    int idx_W1 = -1, idx_b1 = -1;
    int idx_W_a = -1, idx_W_b = -1, idx_b_a = -1, idx_b_b = -1;
    for (int i = 0; i < n_in; i++) {
        if (i == i1 || i == i2) continue;
        int s = in_sizes[i];
        if (s == F_IN * F_H) idx_W1 = i;
        else if (s == F_H) idx_b1 = i;
        else if (s == F_H * F_OUT) { if (idx_W_a < 0) idx_W_a = i; else idx_W_b = i; }
        else if (s == F_OUT) { if (idx_b_a < 0) idx_b_a = i; else idx_b_b = i; }
    }
    int min_big = (i1 < i2) ? i1 : i2;
    int mu_first = (min_big == 0) ? 1 : 0;
    int idx_Wmu = mu_first ? idx_W_a : idx_W_b;
    int idx_Wls = mu_first ? idx_W_b : idx_W_a;
    int idx_bmu = mu_first ? idx_b_a : idx_b_b;
    int idx_bls = mu_first ? idx_b_b : idx_b_a;

    int ca = (i1 < i2) ? i1 : i2;
    int cb = (i1 < i2) ? i2 : i1;
    const float* c0 = (const float*)d_in[ca];
    const float* c1 = (const float*)d_in[cb];

    int e, host_eisel = 0;
    if (tie) {
        e = in_sizes[ca] / 4;
        if (n <= 0) n = in_sizes[ca] / F_IN;
    } else {
        int idx_x  = (in_sizes[ca] > in_sizes[cb]) ? ca : cb;
        int idx_ei = (idx_x == ca) ? cb : ca;
        e = in_sizes[idx_ei] / 2;
        host_eisel = (idx_ei == cb) ? 1 : 0;
        if (n <= 0) n = in_sizes[idx_x] / F_IN;
    }
    if (n > N_NODES) n = N_NODES;
    if (e > N_EDGES) e = N_EDGES;

    const float* W1  = (const float*)d_in[idx_W1];
    const float* b1  = (const float*)d_in[idx_b1];
    const float* Wmu = (const float*)d_in[idx_Wmu];
    const float* bmu = (const float*)d_in[idx_bmu];
    const float* Wls = (const float*)d_in[idx_Wls];
    const float* bls = (const float*)d_in[idx_bls];
    float* out = (float*)d_out;

    k_zero_probe  <<<(n + 255) / 256, 256>>>((const int*)c0, (const int*)c1, tie, host_eisel, n);
    k_decode_count<<<(e + 255) / 256, 256>>>((const void*)c0, (const void*)c1, e, n);
    k_scan        <<<1, 1024>>>(n);
    k_fill        <<<(e + 255) / 256, 256>>>(e);

    k_gemm1<<<(n + 3) / 4, dim3(64, 4)>>>(c0, c1, W1, n);

    int blocks = (n + 7) / 8;   // 8 warps (256 threads) per block
    k_gather1<<<blocks, 256>>>(b1, n);
    k_gather2<<<blocks, 256>>>(n);

    k_out<<<(n + 7) / 8, dim3(32, 8)>>>(Wmu, bmu, Wls, bls, out, n);
}

// round 7
// speedup vs baseline: 1.2415x; 1.2415x over previous
#include <cuda_runtime.h>
#include <cuda_fp16.h>
#include <stdint.h>

#define N_NODES 50000
#define N_EDGES 1600000
#define F_IN 128
#define F_H  64
#define F_OUT 32

// ---------------- device scratch (no allocations allowed) ----------------
__device__ int     g_is64;
__device__ int     g_eisel;
__device__ int     g_row[N_EDGES];
__device__ int     g_col[N_EDGES];
__device__ int     g_rank[N_EDGES];           // per-edge rank within its col
__device__ int     g_cnt[N_NODES];
__device__ int     g_off[N_NODES + 1];
__device__ float   g_dinv[N_NODES];
__device__ int2    g_csr[N_EDGES];            // {row, norm bits}
__device__ __half2 g_h0[N_NODES * (F_H / 2)]; // x @ W1   (fp16 pairs)
__device__ __half2 g_h [N_NODES * (F_H / 2)]; // relu(A_hat h0 + b1)
__device__ float2  g_g [N_NODES * (F_H / 2)]; // A_hat h  (fp32)

// packed fp32x2 FMA (Blackwell FFMA2) helpers
__device__ __forceinline__ unsigned long long pack2(float lo, float hi) {
    unsigned long long r;
    asm("mov.b64 %0, {%1, %2};" : "=l"(r) : "r"(__float_as_uint(lo)), "r"(__float_as_uint(hi)));
    return r;
}
__device__ __forceinline__ void fma2(unsigned long long& acc, unsigned long long a,
                                     unsigned long long b) {
    asm("fma.rn.f32x2 %0, %1, %2, %0;" : "+l"(acc) : "l"(a), "l"(b));
}
__device__ __forceinline__ float lo2(unsigned long long v) {
    return __uint_as_float((unsigned)(v & 0xFFFFFFFFull));
}
__device__ __forceinline__ float hi2(unsigned long long v) {
    return __uint_as_float((unsigned)(v >> 32));
}

// ---------------- zero + probe (fused) ----------------
__global__ void k_zero_probe(const int* __restrict__ c0, const int* __restrict__ c1,
                             int tie, int host_eisel, int n) {
    int i = blockIdx.x * blockDim.x + threadIdx.x;
    if (i < n) g_cnt[i] = 0;
    if (i == 0) {
        if (tie) {
            int any0 = 0;
            for (int k = 1; k < 2048; k += 2) any0 |= c0[k];
            g_eisel = (any0 == 0) ? 0 : 1;
            g_is64 = 1;
        } else {
            g_eisel = host_eisel;
            const int* w = host_eisel ? c1 : c0;
            int any = 0;
            for (int k = 1; k < 2048; k += 2) any |= w[k];
            g_is64 = (any == 0) ? 1 : 0;
        }
    }
}

// ---------------- decode + degree count + rank (fused) ----------------
__global__ void k_decode_count(const void* __restrict__ c0, const void* __restrict__ c1,
                               int e, int n) {
    int i = blockIdx.x * blockDim.x + threadIdx.x;
    if (i >= e) return;
    const void* p = g_eisel ? c1 : c0;
    int r, c;
    if (g_is64) {
        const long long* q = (const long long*)p;
        r = (int)q[i];
        c = (int)q[e + i];
    } else {
        const int* q = (const int*)p;
        r = q[i];
        c = q[e + i];
    }
    if ((unsigned)r >= (unsigned)n) r = 0;
    if ((unsigned)c >= (unsigned)n) c = 0;
    g_row[i] = r;
    g_col[i] = c;
    g_rank[i] = atomicAdd(&g_cnt[c], 1);
}

// ---------------- scan + dinv (fused single block) ----------------
__global__ void k_scan(int n) {
    __shared__ int s[1024];
    int t = threadIdx.x;
    int ch = (n + 1023) >> 10;
    int start = t * ch;
    int sum = 0;
    for (int i = 0; i < ch; i++) {
        int idx = start + i;
        if (idx < n) sum += g_cnt[idx];
    }
    s[t] = sum;
    __syncthreads();
    for (int d = 1; d < 1024; d <<= 1) {
        int v = (t >= d) ? s[t - d] : 0;
        __syncthreads();
        s[t] += v;
        __syncthreads();
    }
    int run = (t == 0) ? 0 : s[t - 1];
    for (int i = 0; i < ch; i++) {
        int idx = start + i;
        if (idx < n) {
            g_off[idx] = run;
            int cnt = g_cnt[idx];
            run += cnt;
            g_dinv[idx] = rsqrtf((float)cnt + 1.0f);
        }
    }
    if (t == 1023) g_off[n] = run;
}

// ---------------- fill packed CSR (no atomics: rank precomputed) ----------------
__global__ void k_fill(int e) {
    int i = blockIdx.x * blockDim.x + threadIdx.x;
    if (i < e) {
        int row = g_row[i];
        int col = g_col[i];
        int pos = g_off[col] + g_rank[i];
        float nrm = g_dinv[row] * g_dinv[col];
        g_csr[pos] = make_int2(row, __float_as_int(nrm));
    }
}

// ---------------- h0 = x @ W1 (128->64), 32 nodes/block, f32x2 FMA ----------------
__global__ void k_gemm1(const float* __restrict__ c0, const float* __restrict__ c1,
                        const float* __restrict__ W1, int n) {
    __shared__ float Ws[F_IN * F_H];       // 32 KB, [k][feat]
    __shared__ float xsT[F_IN][34];        // [k][node], padded (even pad -> 8B aligned pairs)
    const float* x = g_eisel ? c0 : c1;
    int tx = threadIdx.x;                  // 0..63 : out feature
    int ty = threadIdx.y;                  // 0..3  : node octet
    int tid = ty * 64 + tx;
    int node0 = blockIdx.x * 32;
    for (int i = tid; i < F_IN * F_H; i += 256) Ws[i] = W1[i];
    for (int idx = tid; idx < 32 * F_IN; idx += 256) {
        int nd = idx >> 7;                 // node within block
        int k  = idx & 127;
        int node = node0 + nd;
        xsT[k][nd] = (node < n) ? x[(size_t)node * F_IN + k] : 0.0f;
    }
    __syncthreads();
    unsigned long long acc[4] = {0ull, 0ull, 0ull, 0ull};  // 4 node-pairs (8 nodes)
    int nb = ty * 8;
#pragma unroll 8
    for (int k = 0; k < F_IN; k++) {
        float w = Ws[k * F_H + tx];
        unsigned long long w2 = pack2(w, w);
#pragma unroll
        for (int p = 0; p < 4; p++) {
            unsigned long long a2 = *(const unsigned long long*)&xsT[k][nb + 2 * p];
            fma2(acc[p], a2, w2);
        }
    }
    __half* h0 = (__half*)g_h0;
#pragma unroll
    for (int p = 0; p < 4; p++) {
        int n_lo = node0 + nb + 2 * p;
        int n_hi = n_lo + 1;
        if (n_lo < n) h0[n_lo * F_H + tx] = __float2half_rn(lo2(acc[p]));
        if (n_hi < n) h0[n_hi * F_H + tx] = __float2half_rn(hi2(acc[p]));
    }
}

// ---------------- warp-per-node gathers ----------------
// h = relu(A_hat h0 + b1)
__global__ void k_gather1(const float* __restrict__ bias, int n) {
    int warp = (blockIdx.x * blockDim.x + threadIdx.x) >> 5;
    int lane = threadIdx.x & 31;
    if (warp >= n) return;
    float di = g_dinv[warp];
    float sl = di * di;
    float2 fs = __half22float2(g_h0[warp * 32 + lane]);
    float a0 = fs.x * sl;
    float a1 = fs.y * sl;
    int s = g_off[warp], e = g_off[warp + 1];
#pragma unroll 4
    for (int j = s; j < e; j++) {
        int2 m = __ldg(&g_csr[j]);
        float w = __int_as_float(m.y);
        float2 f = __half22float2(__ldg(&g_h0[m.x * 32 + lane]));
        a0 = fmaf(f.x, w, a0);
        a1 = fmaf(f.y, w, a1);
    }
    float2 b = ((const float2*)bias)[lane];
    a0 = fmaxf(a0 + b.x, 0.0f);
    a1 = fmaxf(a1 + b.y, 0.0f);
    g_h[warp * 32 + lane] = __floats2half2_rn(a0, a1);
}

// g = A_hat h   (fp32 out)
__global__ void k_gather2(int n) {
    int warp = (blockIdx.x * blockDim.x + threadIdx.x) >> 5;
    int lane = threadIdx.x & 31;
    if (warp >= n) return;
    float di = g_dinv[warp];
    float sl = di * di;
    float2 fs = __half22float2(g_h[warp * 32 + lane]);
    float a0 = fs.x * sl;
    float a1 = fs.y * sl;
    int s = g_off[warp], e = g_off[warp + 1];
#pragma unroll 4
    for (int j = s; j < e; j++) {
        int2 m = __ldg(&g_csr[j]);
        float w = __int_as_float(m.y);
        float2 f = __half22float2(__ldg(&g_h[m.x * 32 + lane]));
        a0 = fmaf(f.x, w, a0);
        a1 = fmaf(f.y, w, a1);
    }
    g_g[warp * 32 + lane] = make_float2(a0, a1);
}

// ---------------- output heads: 32 nodes/block, f32x2 FMA ----------------
__global__ void k_out(const float* __restrict__ Wmu, const float* __restrict__ bmu,
                      const float* __restrict__ Wls, const float* __restrict__ bls,
                      float* __restrict__ out, int n) {
    __shared__ float Wm[F_H * F_OUT];      // [k][f], 8 KB
    __shared__ float Wl[F_H * F_OUT];
    __shared__ float gsT[F_H][34];         // [k][node], padded
    int tx = threadIdx.x;                  // 0..31 : out feature
    int ty = threadIdx.y;                  // 0..7  : node quartet
    int tid = ty * 32 + tx;
    int node0 = blockIdx.x * 32;
    for (int i = tid; i < F_H * F_OUT; i += 256) { Wm[i] = Wmu[i]; Wl[i] = Wls[i]; }
    const float* gg = (const float*)g_g;
    for (int idx = tid; idx < 32 * F_H; idx += 256) {
        int nd = idx >> 6;
        int k  = idx & 63;
        int node = node0 + nd;
        gsT[k][nd] = (node < n) ? gg[(size_t)node * F_H + k] : 0.0f;
    }
    __syncthreads();
    unsigned long long am[2] = {0ull, 0ull};
    unsigned long long al[2] = {0ull, 0ull};
    int nb = ty * 4;
#pragma unroll 8
    for (int k = 0; k < F_H; k++) {
        float wm = Wm[k * F_OUT + tx];
        float wl = Wl[k * F_OUT + tx];
        unsigned long long wm2 = pack2(wm, wm);
        unsigned long long wl2 = pack2(wl, wl);
#pragma unroll
        for (int p = 0; p < 2; p++) {
            unsigned long long a2 = *(const unsigned long long*)&gsT[k][nb + 2 * p];
            fma2(am[p], a2, wm2);
            fma2(al[p], a2, wl2);
        }
    }
    float bm = bmu[tx], bl = bls[tx];
#pragma unroll
    for (int p = 0; p < 2; p++) {
        int n_lo = node0 + nb + 2 * p;
        int n_hi = n_lo + 1;
        if (n_lo < n) {
            out[(size_t)n_lo * F_OUT + tx]                       = lo2(am[p]) + bm;
            out[(size_t)n * F_OUT + (size_t)n_lo * F_OUT + tx]   = lo2(al[p]) + bl;
        }
        if (n_hi < n) {
            out[(size_t)n_hi * F_OUT + tx]                       = hi2(am[p]) + bm;
            out[(size_t)n * F_OUT + (size_t)n_hi * F_OUT + tx]   = hi2(al[p]) + bl;
        }
    }
}

// ---------------- launch ----------------
extern "C" void kernel_launch(void* const* d_in, const int* in_sizes, int n_in,
                              void* d_out, int out_size) {
    int n = out_size / (2 * F_OUT);

    long long best1 = -1, best2 = -1; int i1 = -1, i2 = -1;
    for (int i = 0; i < n_in; i++) {
        long long s = in_sizes[i];
        if (s > best1) { best2 = best1; i2 = i1; best1 = s; i1 = i; }
        else if (s > best2) { best2 = s; i2 = i; }
    }
    int tie = (best1 == best2);

    int idx_W1 = -1, idx_b1 = -1;
    int idx_W_a = -1, idx_W_b = -1, idx_b_a = -1, idx_b_b = -1;
    for (int i = 0; i < n_in; i++) {
        if (i == i1 || i == i2) continue;
        int s = in_sizes[i];
        if (s == F_IN * F_H) idx_W1 = i;
        else if (s == F_H) idx_b1 = i;
        else if (s == F_H * F_OUT) { if (idx_W_a < 0) idx_W_a = i; else idx_W_b = i; }
        else if (s == F_OUT) { if (idx_b_a < 0) idx_b_a = i; else idx_b_b = i; }
    }
    int min_big = (i1 < i2) ? i1 : i2;
    int mu_first = (min_big == 0) ? 1 : 0;
    int idx_Wmu = mu_first ? idx_W_a : idx_W_b;
    int idx_Wls = mu_first ? idx_W_b : idx_W_a;
    int idx_bmu = mu_first ? idx_b_a : idx_b_b;
    int idx_bls = mu_first ? idx_b_b : idx_b_a;

    int ca = (i1 < i2) ? i1 : i2;
    int cb = (i1 < i2) ? i2 : i1;
    const float* c0 = (const float*)d_in[ca];
    const float* c1 = (const float*)d_in[cb];

    int e, host_eisel = 0;
    if (tie) {
        e = in_sizes[ca] / 4;
        if (n <= 0) n = in_sizes[ca] / F_IN;
    } else {
        int idx_x  = (in_sizes[ca] > in_sizes[cb]) ? ca : cb;
        int idx_ei = (idx_x == ca) ? cb : ca;
        e = in_sizes[idx_ei] / 2;
        host_eisel = (idx_ei == cb) ? 1 : 0;
        if (n <= 0) n = in_sizes[idx_x] / F_IN;
    }
    if (n > N_NODES) n = N_NODES;
    if (e > N_EDGES) e = N_EDGES;

    const float* W1  = (const float*)d_in[idx_W1];
    const float* b1  = (const float*)d_in[idx_b1];
    const float* Wmu = (const float*)d_in[idx_Wmu];
    const float* bmu = (const float*)d_in[idx_bmu];
    const float* Wls = (const float*)d_in[idx_Wls];
    const float* bls = (const float*)d_in[idx_bls];
    float* out = (float*)d_out;

    k_zero_probe  <<<(n + 255) / 256, 256>>>((const int*)c0, (const int*)c1, tie, host_eisel, n);
    k_decode_count<<<(e + 255) / 256, 256>>>((const void*)c0, (const void*)c1, e, n);
    k_scan        <<<1, 1024>>>(n);
    k_fill        <<<(e + 255) / 256, 256>>>(e);

    k_gemm1<<<(n + 31) / 32, dim3(64, 4)>>>(c0, c1, W1, n);

    int blocks = (n + 7) / 8;   // 8 warps (256 threads) per block
    k_gather1<<<blocks, 256>>>(b1, n);
    k_gather2<<<blocks, 256>>>(n);

    k_out<<<(n + 31) / 32, dim3(32, 8)>>>(Wmu, bmu, Wls, bls, out, n);
}

// round 9
// speedup vs baseline: 1.3518x; 1.0889x over previous
#include <cuda_runtime.h>
#include <cuda_fp16.h>
#include <stdint.h>

#define N_NODES 50000
#define N_EDGES 1600000
#define F_IN 128
#define F_H  64
#define F_OUT 32

// ---------------- device scratch (no allocations allowed) ----------------
__device__ int     g_is64;
__device__ int     g_eisel;
__device__ int     g_rank[N_EDGES];           // per-edge rank within its col
__device__ int     g_cnt[N_NODES];
__device__ int     g_off[N_NODES + 1];
__device__ float   g_dinv[N_NODES];
__device__ int     g_csr_row[N_EDGES];        // row indices only (norm folded out)
__device__ __half2 g_h0[N_NODES * (F_H / 2)]; // dinv * (x @ W1)      (pre-scaled fp16)
__device__ __half2 g_h [N_NODES * (F_H / 2)]; // dinv * relu(layer1)  (pre-scaled fp16)

// packed fp32x2 FMA (Blackwell FFMA2) helpers
__device__ __forceinline__ unsigned long long pack2(float lo, float hi) {
    unsigned long long r;
    asm("mov.b64 %0, {%1, %2};" : "=l"(r) : "r"(__float_as_uint(lo)), "r"(__float_as_uint(hi)));
    return r;
}
__device__ __forceinline__ void fma2(unsigned long long& acc, unsigned long long a,
                                     unsigned long long b) {
    asm("fma.rn.f32x2 %0, %1, %2, %0;" : "+l"(acc) : "l"(a), "l"(b));
}
__device__ __forceinline__ float lo2(unsigned long long v) {
    return __uint_as_float((unsigned)(v & 0xFFFFFFFFull));
}
__device__ __forceinline__ float hi2(unsigned long long v) {
    return __uint_as_float((unsigned)(v >> 32));
}

// ---------------- zero + probe (fused, warp-parallel probe) ----------------
__global__ void k_zero_probe(const int* __restrict__ c0, const int* __restrict__ c1,
                             int tie, int host_eisel, int n) {
    int i = blockIdx.x * blockDim.x + threadIdx.x;
    if (i < n) g_cnt[i] = 0;
    if (blockIdx.x == 0 && threadIdx.x < 32) {
        int lane = threadIdx.x;
        if (tie) {
            int any0 = 0;
            for (int k = 1 + 2 * lane; k < 2048; k += 64) any0 |= c0[k];
            any0 = __any_sync(0xffffffffu, any0 != 0);
            if (lane == 0) { g_eisel = any0 ? 1 : 0; g_is64 = 1; }
        } else {
            const int* w = host_eisel ? c1 : c0;
            int any = 0;
            for (int k = 1 + 2 * lane; k < 2048; k += 64) any |= w[k];
            any = __any_sync(0xffffffffu, any != 0);
            if (lane == 0) { g_eisel = host_eisel; g_is64 = any ? 0 : 1; }
        }
    }
}

// ---------------- pass 1: count cols + edge rank (reads col half only) ----------------
__global__ void k_count(const void* __restrict__ c0, const void* __restrict__ c1,
                        int e, int n) {
    int i = blockIdx.x * blockDim.x + threadIdx.x;
    if (i >= e) return;
    const void* p = g_eisel ? c1 : c0;
    int c;
    if (g_is64) c = (int)((const long long*)p)[e + i];
    else        c = ((const int*)p)[e + i];
    if ((unsigned)c >= (unsigned)n) c = 0;
    g_rank[i] = atomicAdd(&g_cnt[c], 1);
}

// ---------------- scan + dinv (fused single block) ----------------
__global__ void k_scan(int n) {
    __shared__ int s[1024];
    int t = threadIdx.x;
    int ch = (n + 1023) >> 10;
    int start = t * ch;
    int sum = 0;
    for (int i = 0; i < ch; i++) {
        int idx = start + i;
        if (idx < n) sum += g_cnt[idx];
    }
    s[t] = sum;
    __syncthreads();
    for (int d = 1; d < 1024; d <<= 1) {
        int v = (t >= d) ? s[t - d] : 0;
        __syncthreads();
        s[t] += v;
        __syncthreads();
    }
    int run = (t == 0) ? 0 : s[t - 1];
    for (int i = 0; i < ch; i++) {
        int idx = start + i;
        if (idx < n) {
            g_off[idx] = run;
            int cnt = g_cnt[idx];
            run += cnt;
            g_dinv[idx] = rsqrtf((float)cnt + 1.0f);
        }
    }
    if (t == 1023) g_off[n] = run;
}

// ---------------- pass 2: fill row-only CSR (re-decode, no atomics) ----------------
__global__ void k_fill(const void* __restrict__ c0, const void* __restrict__ c1,
                       int e, int n) {
    int i = blockIdx.x * blockDim.x + threadIdx.x;
    if (i >= e) return;
    const void* p = g_eisel ? c1 : c0;
    int r, c;
    if (g_is64) {
        const long long* q = (const long long*)p;
        r = (int)q[i];
        c = (int)q[e + i];
    } else {
        const int* q = (const int*)p;
        r = q[i];
        c = q[e + i];
    }
    if ((unsigned)r >= (unsigned)n) r = 0;
    if ((unsigned)c >= (unsigned)n) c = 0;
    g_csr_row[g_off[c] + g_rank[i]] = r;
}

// ---------------- h0' = dinv * (x @ W1), 32 nodes/block, f32x2 FMA ----------------
__global__ void k_gemm1(const float* __restrict__ c0, const float* __restrict__ c1,
                        const float* __restrict__ W1, int n) {
    __shared__ float Ws[F_IN * F_H];       // 32 KB, [k][feat]
    __shared__ float xsT[F_IN][34];        // [k][node], padded
    const float* x = g_eisel ? c0 : c1;
    int tx = threadIdx.x;                  // 0..63 : out feature
    int ty = threadIdx.y;                  // 0..3  : node octet
    int tid = ty * 64 + tx;
    int node0 = blockIdx.x * 32;
    for (int i = tid; i < F_IN * F_H; i += 256) Ws[i] = W1[i];
    for (int idx = tid; idx < 32 * F_IN; idx += 256) {
        int nd = idx >> 7;
        int k  = idx & 127;
        int node = node0 + nd;
        xsT[k][nd] = (node < n) ? x[(size_t)node * F_IN + k] : 0.0f;
    }
    __syncthreads();
    unsigned long long acc[4] = {0ull, 0ull, 0ull, 0ull};
    int nb = ty * 8;
#pragma unroll 8
    for (int k = 0; k < F_IN; k++) {
        float w = Ws[k * F_H + tx];
        unsigned long long w2 = pack2(w, w);
#pragma unroll
        for (int p = 0; p < 4; p++) {
            unsigned long long a2 = *(const unsigned long long*)&xsT[k][nb + 2 * p];
            fma2(acc[p], a2, w2);
        }
    }
    __half* h0 = (__half*)g_h0;
#pragma unroll
    for (int p = 0; p < 4; p++) {
        int n_lo = node0 + nb + 2 * p;
        int n_hi = n_lo + 1;
        if (n_lo < n) h0[n_lo * F_H + tx] = __float2half_rn(lo2(acc[p]) * g_dinv[n_lo]);
        if (n_hi < n) h0[n_hi * F_H + tx] = __float2half_rn(hi2(acc[p]) * g_dinv[n_hi]);
    }
}

// ---------------- gather1: h' = dinv * relu(dinv*(sum h0') + b) ----------------
// lane holds features (2*lane, 2*lane+1)
__global__ void k_gather1(const float* __restrict__ bias, int n) {
    int warp = (blockIdx.x * blockDim.x + threadIdx.x) >> 5;
    int lane = threadIdx.x & 31;
    if (warp >= n) return;
    float di = g_dinv[warp];
    float2 own = __half22float2(g_h0[warp * 32 + lane]);
    float a0 = own.x, a1 = own.y;
    int s = g_off[warp], e = g_off[warp + 1];
    for (int j = s; j < e; j += 32) {
        int cnt = e - j; if (cnt > 32) cnt = 32;
        int r = (lane < cnt) ? __ldg(&g_csr_row[j + lane]) : 0;
#pragma unroll 4
        for (int t = 0; t < cnt; t++) {
            int rr = __shfl_sync(0xffffffffu, r, t);
            float2 f = __half22float2(__ldg(&g_h0[rr * 32 + lane]));
            a0 += f.x;
            a1 += f.y;
        }
    }
    float2 b = ((const float2*)bias)[lane];   // bias features (2*lane, 2*lane+1)
    a0 = fmaxf(fmaf(a0, di, b.x), 0.0f);
    a1 = fmaxf(fmaf(a1, di, b.y), 0.0f);
    g_h[warp * 32 + lane] = __floats2half2_rn(a0 * di, a1 * di);
}

// ---------------- gather2 + output heads (fused, grid-strided) ----------------
__global__ void k_g2out(const float* __restrict__ Wmu, const float* __restrict__ bmu,
                        const float* __restrict__ Wls, const float* __restrict__ bls,
                        float* __restrict__ out, int n) {
    __shared__ float Wm[F_H * F_OUT];   // 8 KB
    __shared__ float Wl[F_H * F_OUT];   // 8 KB
    int tid = threadIdx.x;
    int lane = tid & 31;
    for (int i = tid; i < F_H * F_OUT; i += 256) { Wm[i] = Wmu[i]; Wl[i] = Wls[i]; }
    __syncthreads();
    float bm = bmu[lane], bl = bls[lane];
    int gw = blockIdx.x * 8 + (tid >> 5);
    int stride = gridDim.x * 8;
    for (int node = gw; node < n; node += stride) {
        float di = g_dinv[node];
        float2 own = __half22float2(g_h[node * 32 + lane]);
        float a0 = own.x, a1 = own.y;    // features 2*lane, 2*lane+1
        int s = g_off[node], e = g_off[node + 1];
        for (int j = s; j < e; j += 32) {
            int cnt = e - j; if (cnt > 32) cnt = 32;
            int r = (lane < cnt) ? __ldg(&g_csr_row[j + lane]) : 0;
#pragma unroll 4
            for (int t = 0; t < cnt; t++) {
                int rr = __shfl_sync(0xffffffffu, r, t);
                float2 f = __half22float2(__ldg(&g_h[rr * 32 + lane]));
                a0 += f.x;
                a1 += f.y;
            }
        }
        a0 *= di;   // g feature 2*lane
        a1 *= di;   // g feature 2*lane+1
        float mu = 0.0f, ls = 0.0f;
        // lane t of a0 holds feature 2t; lane t of a1 holds feature 2t+1
#pragma unroll
        for (int k = 0; k < 32; k++) {
            float gx = __shfl_sync(0xffffffffu, a0, k);   // feature 2k
            float gy = __shfl_sync(0xffffffffu, a1, k);   // feature 2k+1
            mu = fmaf(gx, Wm[(2 * k)     * F_OUT + lane], mu);
            mu = fmaf(gy, Wm[(2 * k + 1) * F_OUT + lane], mu);
            ls = fmaf(gx, Wl[(2 * k)     * F_OUT + lane], ls);
            ls = fmaf(gy, Wl[(2 * k + 1) * F_OUT + lane], ls);
        }
        out[(size_t)node * F_OUT + lane]                        = mu + bm;
        out[(size_t)n * F_OUT + (size_t)node * F_OUT + lane]    = ls + bl;
    }
}

// ---------------- launch ----------------
extern "C" void kernel_launch(void* const* d_in, const int* in_sizes, int n_in,
                              void* d_out, int out_size) {
    int n = out_size / (2 * F_OUT);

    long long best1 = -1, best2 = -1; int i1 = -1, i2 = -1;
    for (int i = 0; i < n_in; i++) {
        long long s = in_sizes[i];
        if (s > best1) { best2 = best1; i2 = i1; best1 = s; i1 = i; }
        else if (s > best2) { best2 = s; i2 = i; }
    }
    int tie = (best1 == best2);

    int idx_W1 = -1, idx_b1 = -1;
    int idx_W_a = -1, idx_W_b = -1, idx_b_a = -1, idx_b_b = -1;
    for (int i = 0; i < n_in; i++) {
        if (i == i1 || i == i2) continue;
        int s = in_sizes[i];
        if (s == F_IN * F_H) idx_W1 = i;
        else if (s == F_H) idx_b1 = i;
        else if (s == F_H * F_OUT) { if (idx_W_a < 0) idx_W_a = i; else idx_W_b = i; }
        else if (s == F_OUT) { if (idx_b_a < 0) idx_b_a = i; else idx_b_b = i; }
    }
    int min_big = (i1 < i2) ? i1 : i2;
    int mu_first = (min_big == 0) ? 1 : 0;
    int idx_Wmu = mu_first ? idx_W_a : idx_W_b;
    int idx_Wls = mu_first ? idx_W_b : idx_W_a;
    int idx_bmu = mu_first ? idx_b_a : idx_b_b;
    int idx_bls = mu_first ? idx_b_b : idx_b_a;

    int ca = (i1 < i2) ? i1 : i2;
    int cb = (i1 < i2) ? i2 : i1;
    const float* c0 = (const float*)d_in[ca];
    const float* c1 = (const float*)d_in[cb];

    int e, host_eisel = 0;
    if (tie) {
        e = in_sizes[ca] / 4;
        if (n <= 0) n = in_sizes[ca] / F_IN;
    } else {
        int idx_x  = (in_sizes[ca] > in_sizes[cb]) ? ca : cb;
        int idx_ei = (idx_x == ca) ? cb : ca;
        e = in_sizes[idx_ei] / 2;
        host_eisel = (idx_ei == cb) ? 1 : 0;
        if (n <= 0) n = in_sizes[idx_x] / F_IN;
    }
    if (n > N_NODES) n = N_NODES;
    if (e > N_EDGES) e = N_EDGES;

    const float* W1  = (const float*)d_in[idx_W1];
    const float* b1  = (const float*)d_in[idx_b1];
    const float* Wmu = (const float*)d_in[idx_Wmu];
    const float* bmu = (const float*)d_in[idx_bmu];
    const float* Wls = (const float*)d_in[idx_Wls];
    const float* bls = (const float*)d_in[idx_bls];
    float* out = (float*)d_out;

    k_zero_probe<<<(n + 255) / 256, 256>>>((const int*)c0, (const int*)c1, tie, host_eisel, n);
    k_count     <<<(e + 255) / 256, 256>>>((const void*)c0, (const void*)c1, e, n);
    k_scan      <<<1, 1024>>>(n);
    k_fill      <<<(e + 255) / 256, 256>>>((const void*)c0, (const void*)c1, e, n);

    k_gemm1<<<(n + 31) / 32, dim3(64, 4)>>>(c0, c1, W1, n);

    k_gather1<<<(n + 7) / 8, 256>>>(b1, n);
    k_g2out  <<<592, 256>>>(Wmu, bmu, Wls, bls, out, n);
}

// round 10
// speedup vs baseline: 1.8717x; 1.3845x over previous
#include <cuda_runtime.h>
#include <cuda_fp16.h>
#include <stdint.h>

#define N_NODES 50000
#define N_EDGES 1600000
#define F_IN 128
#define F_H  64
#define F_OUT 32
#define SCAN_BLK 1024

// ---------------- device scratch (no allocations allowed) ----------------
__device__ int     g_is64;
__device__ int     g_eisel;
__device__ int     g_rank[N_EDGES];           // per-edge rank within its col
__device__ int     g_cnt[N_NODES];
__device__ int     g_off[N_NODES + 1];
__device__ int     g_bsum[64];                // block sums for two-level scan
__device__ float   g_dinv[N_NODES];
__device__ int     g_csr_row[N_EDGES];        // row indices only (norm folded out)
__device__ __half2 g_h0[N_NODES * (F_H / 2)]; // dinv * (x @ W1)      (pre-scaled fp16)
__device__ __half2 g_h [N_NODES * (F_H / 2)]; // dinv * relu(layer1)  (pre-scaled fp16)

// packed fp32x2 FMA (Blackwell FFMA2) helpers
__device__ __forceinline__ unsigned long long pack2(float lo, float hi) {
    unsigned long long r;
    asm("mov.b64 %0, {%1, %2};" : "=l"(r) : "r"(__float_as_uint(lo)), "r"(__float_as_uint(hi)));
    return r;
}
__device__ __forceinline__ void fma2(unsigned long long& acc, unsigned long long a,
                                     unsigned long long b) {
    asm("fma.rn.f32x2 %0, %1, %2, %0;" : "+l"(acc) : "l"(a), "l"(b));
}
__device__ __forceinline__ float lo2(unsigned long long v) {
    return __uint_as_float((unsigned)(v & 0xFFFFFFFFull));
}
__device__ __forceinline__ float hi2(unsigned long long v) {
    return __uint_as_float((unsigned)(v >> 32));
}

// ---------------- zero + probe (fused, warp-parallel probe) ----------------
__global__ void k_zero_probe(const int* __restrict__ c0, const int* __restrict__ c1,
                             int tie, int host_eisel, int n) {
    int i = blockIdx.x * blockDim.x + threadIdx.x;
    if (i < n) g_cnt[i] = 0;
    if (blockIdx.x == 0 && threadIdx.x < 32) {
        int lane = threadIdx.x;
        if (tie) {
            int any0 = 0;
            for (int k = 1 + 2 * lane; k < 2048; k += 64) any0 |= c0[k];
            any0 = __any_sync(0xffffffffu, any0 != 0);
            if (lane == 0) { g_eisel = any0 ? 1 : 0; g_is64 = 1; }
        } else {
            const int* w = host_eisel ? c1 : c0;
            int any = 0;
            for (int k = 1 + 2 * lane; k < 2048; k += 64) any |= w[k];
            any = __any_sync(0xffffffffu, any != 0);
            if (lane == 0) { g_eisel = host_eisel; g_is64 = any ? 0 : 1; }
        }
    }
}

// ---------------- pass 1: count cols + edge rank (reads col half only) ----------------
__global__ void k_count(const void* __restrict__ c0, const void* __restrict__ c1,
                        int e, int n) {
    int i = blockIdx.x * blockDim.x + threadIdx.x;
    if (i >= e) return;
    const void* p = g_eisel ? c1 : c0;
    int c;
    if (g_is64) c = (int)((const long long*)p)[e + i];
    else        c = ((const int*)p)[e + i];
    if ((unsigned)c >= (unsigned)n) c = 0;
    g_rank[i] = atomicAdd(&g_cnt[c], 1);
}

// ---------------- two-level parallel scan + dinv ----------------
__global__ void k_scan1(int n) {
    __shared__ int s[SCAN_BLK];
    int t = threadIdx.x;
    int i = blockIdx.x * SCAN_BLK + t;
    int v = (i < n) ? g_cnt[i] : 0;
    s[t] = v;
    __syncthreads();
    for (int d = 1; d < SCAN_BLK; d <<= 1) {
        int u = (t >= d) ? s[t - d] : 0;
        __syncthreads();
        s[t] += u;
        __syncthreads();
    }
    if (i < n) {
        g_off[i]  = s[t] - v;                     // block-local exclusive
        g_dinv[i] = rsqrtf((float)v + 1.0f);
    }
    if (t == SCAN_BLK - 1) g_bsum[blockIdx.x] = s[t];
}

__global__ void k_scan2(int nb, int n) {
    __shared__ int s[64];
    int t = threadIdx.x;                          // 64 threads
    int v = (t < nb) ? g_bsum[t] : 0;
    s[t] = v;
    __syncthreads();
    for (int d = 1; d < 64; d <<= 1) {
        int u = (t >= d) ? s[t - d] : 0;
        __syncthreads();
        s[t] += u;
        __syncthreads();
    }
    if (t < nb) g_bsum[t] = s[t] - v;             // exclusive block offsets
    if (t == nb - 1) g_off[n] = s[t];             // grand total
}

__global__ void k_scan3(int n) {
    int i = blockIdx.x * blockDim.x + threadIdx.x;
    if (i < n) g_off[i] += g_bsum[i >> 10];
}

// ---------------- pass 2: fill row-only CSR (re-decode, no atomics) ----------------
__global__ void k_fill(const void* __restrict__ c0, const void* __restrict__ c1,
                       int e, int n) {
    int i = blockIdx.x * blockDim.x + threadIdx.x;
    if (i >= e) return;
    const void* p = g_eisel ? c1 : c0;
    int r, c;
    if (g_is64) {
        const long long* q = (const long long*)p;
        r = (int)q[i];
        c = (int)q[e + i];
    } else {
        const int* q = (const int*)p;
        r = q[i];
        c = q[e + i];
    }
    if ((unsigned)r >= (unsigned)n) r = 0;
    if ((unsigned)c >= (unsigned)n) c = 0;
    g_csr_row[g_off[c] + g_rank[i]] = r;
}

// ---------------- h0' = dinv * (x @ W1), 32 nodes/block, f32x2 FMA ----------------
__global__ void k_gemm1(const float* __restrict__ c0, const float* __restrict__ c1,
                        const float* __restrict__ W1, int n) {
    __shared__ float Ws[F_IN * F_H];       // 32 KB, [k][feat]
    __shared__ float xsT[F_IN][34];        // [k][node], padded
    const float* x = g_eisel ? c0 : c1;
    int tx = threadIdx.x;                  // 0..63 : out feature
    int ty = threadIdx.y;                  // 0..3  : node octet
    int tid = ty * 64 + tx;
    int node0 = blockIdx.x * 32;
    for (int i = tid; i < F_IN * F_H; i += 256) Ws[i] = W1[i];
    for (int idx = tid; idx < 32 * F_IN; idx += 256) {
        int nd = idx >> 7;
        int k  = idx & 127;
        int node = node0 + nd;
        xsT[k][nd] = (node < n) ? x[(size_t)node * F_IN + k] : 0.0f;
    }
    __syncthreads();
    unsigned long long acc[4] = {0ull, 0ull, 0ull, 0ull};
    int nb = ty * 8;
#pragma unroll 8
    for (int k = 0; k < F_IN; k++) {
        float w = Ws[k * F_H + tx];
        unsigned long long w2 = pack2(w, w);
#pragma unroll
        for (int p = 0; p < 4; p++) {
            unsigned long long a2 = *(const unsigned long long*)&xsT[k][nb + 2 * p];
            fma2(acc[p], a2, w2);
        }
    }
    __half* h0 = (__half*)g_h0;
#pragma unroll
    for (int p = 0; p < 4; p++) {
        int n_lo = node0 + nb + 2 * p;
        int n_hi = n_lo + 1;
        if (n_lo < n) h0[n_lo * F_H + tx] = __float2half_rn(lo2(acc[p]) * g_dinv[n_lo]);
        if (n_hi < n) h0[n_hi * F_H + tx] = __float2half_rn(hi2(acc[p]) * g_dinv[n_hi]);
    }
}

// ---------------- gather1: h' = dinv * relu(dinv*(sum h0') + b) ----------------
// lane holds features (2*lane, 2*lane+1)
__global__ void k_gather1(const float* __restrict__ bias, int n) {
    int warp = (blockIdx.x * blockDim.x + threadIdx.x) >> 5;
    int lane = threadIdx.x & 31;
    if (warp >= n) return;
    float di = g_dinv[warp];
    float2 own = __half22float2(g_h0[warp * 32 + lane]);
    float a0 = own.x, a1 = own.y;
    int s = g_off[warp], e = g_off[warp + 1];
    for (int j = s; j < e; j += 32) {
        int cnt = e - j; if (cnt > 32) cnt = 32;
        int r = (lane < cnt) ? __ldg(&g_csr_row[j + lane]) : 0;
#pragma unroll 4
        for (int t = 0; t < cnt; t++) {
            int rr = __shfl_sync(0xffffffffu, r, t);
            float2 f = __half22float2(__ldg(&g_h0[rr * 32 + lane]));
            a0 += f.x;
            a1 += f.y;
        }
    }
    float2 b = ((const float2*)bias)[lane];   // bias features (2*lane, 2*lane+1)
    a0 = fmaxf(fmaf(a0, di, b.x), 0.0f);
    a1 = fmaxf(fmaf(a1, di, b.y), 0.0f);
    g_h[warp * 32 + lane] = __floats2half2_rn(a0 * di, a1 * di);
}

// ---------------- gather2 + output heads (fused, grid-strided) ----------------
__global__ void k_g2out(const float* __restrict__ Wmu, const float* __restrict__ bmu,
                        const float* __restrict__ Wls, const float* __restrict__ bls,
                        float* __restrict__ out, int n) {
    __shared__ float Wm[F_H * F_OUT];   // 8 KB
    __shared__ float Wl[F_H * F_OUT];   // 8 KB
    int tid = threadIdx.x;
    int lane = tid & 31;
    for (int i = tid; i < F_H * F_OUT; i += 256) { Wm[i] = Wmu[i]; Wl[i] = Wls[i]; }
    __syncthreads();
    float bm = bmu[lane], bl = bls[lane];
    int gw = blockIdx.x * 8 + (tid >> 5);
    int stride = gridDim.x * 8;
    for (int node = gw; node < n; node += stride) {
        float di = g_dinv[node];
        float2 own = __half22float2(g_h[node * 32 + lane]);
        float a0 = own.x, a1 = own.y;    // features 2*lane, 2*lane+1
        int s = g_off[node], e = g_off[node + 1];
        for (int j = s; j < e; j += 32) {
            int cnt = e - j; if (cnt > 32) cnt = 32;
            int r = (lane < cnt) ? __ldg(&g_csr_row[j + lane]) : 0;
#pragma unroll 4
            for (int t = 0; t < cnt; t++) {
                int rr = __shfl_sync(0xffffffffu, r, t);
                float2 f = __half22float2(__ldg(&g_h[rr * 32 + lane]));
                a0 += f.x;
                a1 += f.y;
            }
        }
        a0 *= di;   // g feature 2*lane
        a1 *= di;   // g feature 2*lane+1
        float mu = 0.0f, ls = 0.0f;
#pragma unroll
        for (int k = 0; k < 32; k++) {
            float gx = __shfl_sync(0xffffffffu, a0, k);   // feature 2k
            float gy = __shfl_sync(0xffffffffu, a1, k);   // feature 2k+1
            mu = fmaf(gx, Wm[(2 * k)     * F_OUT + lane], mu);
            mu = fmaf(gy, Wm[(2 * k + 1) * F_OUT + lane], mu);
            ls = fmaf(gx, Wl[(2 * k)     * F_OUT + lane], ls);
            ls = fmaf(gy, Wl[(2 * k + 1) * F_OUT + lane], ls);
        }
        out[(size_t)node * F_OUT + lane]                        = mu + bm;
        out[(size_t)n * F_OUT + (size_t)node * F_OUT + lane]    = ls + bl;
    }
}

// ---------------- launch ----------------
extern "C" void kernel_launch(void* const* d_in, const int* in_sizes, int n_in,
                              void* d_out, int out_size) {
    int n = out_size / (2 * F_OUT);

    long long best1 = -1, best2 = -1; int i1 = -1, i2 = -1;
    for (int i = 0; i < n_in; i++) {
        long long s = in_sizes[i];
        if (s > best1) { best2 = best1; i2 = i1; best1 = s; i1 = i; }
        else if (s > best2) { best2 = s; i2 = i; }
    }
    int tie = (best1 == best2);

    int idx_W1 = -1, idx_b1 = -1;
    int idx_W_a = -1, idx_W_b = -1, idx_b_a = -1, idx_b_b = -1;
    for (int i = 0; i < n_in; i++) {
        if (i == i1 || i == i2) continue;
        int s = in_sizes[i];
        if (s == F_IN * F_H) idx_W1 = i;
        else if (s == F_H) idx_b1 = i;
        else if (s == F_H * F_OUT) { if (idx_W_a < 0) idx_W_a = i; else idx_W_b = i; }
        else if (s == F_OUT) { if (idx_b_a < 0) idx_b_a = i; else idx_b_b = i; }
    }
    int min_big = (i1 < i2) ? i1 : i2;
    int mu_first = (min_big == 0) ? 1 : 0;
    int idx_Wmu = mu_first ? idx_W_a : idx_W_b;
    int idx_Wls = mu_first ? idx_W_b : idx_W_a;
    int idx_bmu = mu_first ? idx_b_a : idx_b_b;
    int idx_bls = mu_first ? idx_b_b : idx_b_a;

    int ca = (i1 < i2) ? i1 : i2;
    int cb = (i1 < i2) ? i2 : i1;
    const float* c0 = (const float*)d_in[ca];
    const float* c1 = (const float*)d_in[cb];

    int e, host_eisel = 0;
    if (tie) {
        e = in_sizes[ca] / 4;
        if (n <= 0) n = in_sizes[ca] / F_IN;
    } else {
        int idx_x  = (in_sizes[ca] > in_sizes[cb]) ? ca : cb;
        int idx_ei = (idx_x == ca) ? cb : ca;
        e = in_sizes[idx_ei] / 2;
        host_eisel = (idx_ei == cb) ? 1 : 0;
        if (n <= 0) n = in_sizes[idx_x] / F_IN;
    }
    if (n > N_NODES) n = N_NODES;
    if (e > N_EDGES) e = N_EDGES;

    const float* W1  = (const float*)d_in[idx_W1];
    const float* b1  = (const float*)d_in[idx_b1];
    const float* Wmu = (const float*)d_in[idx_Wmu];
    const float* bmu = (const float*)d_in[idx_bmu];
    const float* Wls = (const float*)d_in[idx_Wls];
    const float* bls = (const float*)d_in[idx_bls];
    float* out = (float*)d_out;

    int nb = (n + SCAN_BLK - 1) / SCAN_BLK;

    k_zero_probe<<<(n + 255) / 256, 256>>>((const int*)c0, (const int*)c1, tie, host_eisel, n);
    k_count     <<<(e + 255) / 256, 256>>>((const void*)c0, (const void*)c1, e, n);
    k_scan1     <<<nb, SCAN_BLK>>>(n);
    k_scan2     <<<1, 64>>>(nb, n);
    k_scan3     <<<(n + 255) / 256, 256>>>(n);
    k_fill      <<<(e + 255) / 256, 256>>>((const void*)c0, (const void*)c1, e, n);

    k_gemm1<<<(n + 31) / 32, dim3(64, 4)>>>(c0, c1, W1, n);

    k_gather1<<<(n + 7) / 8, 256>>>(b1, n);
    k_g2out  <<<592, 256>>>(Wmu, bmu, Wls, bls, out, n);
}

// round 12
// speedup vs baseline: 1.8932x; 1.0115x over previous
#include <cuda_runtime.h>
#include <cuda_fp16.h>
#include <stdint.h>

#define N_NODES 50000
#define N_EDGES 1600000
#define F_IN 128
#define F_H  64
#define F_OUT 32
#define SCAN_BLK 1024

// ---------------- device scratch (no allocations allowed) ----------------
__device__ int     g_is64;
__device__ int     g_eisel;
__device__ int     g_done;                    // scan1 completion counter
__device__ int     g_rank[N_EDGES];           // per-edge rank within its col
__device__ int     g_cnt[N_NODES];
__device__ int     g_off[N_NODES + 1];        // block-LOCAL exclusive offsets
__device__ int     g_bsum[64];                // exclusive block offsets (after scan1)
__device__ float   g_dinv[N_NODES];
__device__ int     g_csr_row[N_EDGES];        // row indices only (norm folded out)
__device__ __half2 g_h0[N_NODES * (F_H / 2)]; // dinv * (x @ W1)      (pre-scaled fp16)
__device__ __half2 g_h [N_NODES * (F_H / 2)]; // dinv * relu(layer1)  (pre-scaled fp16)

// packed fp32x2 FMA (Blackwell FFMA2) helpers
__device__ __forceinline__ unsigned long long pack2(float lo, float hi) {
    unsigned long long r;
    asm("mov.b64 %0, {%1, %2};" : "=l"(r) : "r"(__float_as_uint(lo)), "r"(__float_as_uint(hi)));
    return r;
}
__device__ __forceinline__ void fma2(unsigned long long& acc, unsigned long long a,
                                     unsigned long long b) {
    asm("fma.rn.f32x2 %0, %1, %2, %0;" : "+l"(acc) : "l"(a), "l"(b));
}
__device__ __forceinline__ float lo2(unsigned long long v) {
    return __uint_as_float((unsigned)(v & 0xFFFFFFFFull));
}
__device__ __forceinline__ float hi2(unsigned long long v) {
    return __uint_as_float((unsigned)(v >> 32));
}

// ---------------- zero + probe (fused, warp-parallel probe) ----------------
__global__ void k_zero_probe(const int* __restrict__ c0, const int* __restrict__ c1,
                             int tie, int host_eisel, int n) {
    int i = blockIdx.x * blockDim.x + threadIdx.x;
    if (i < n) g_cnt[i] = 0;
    if (blockIdx.x == 0 && threadIdx.x < 32) {
        int lane = threadIdx.x;
        if (lane == 0) g_done = 0;
        if (tie) {
            int any0 = 0;
            for (int k = 1 + 2 * lane; k < 2048; k += 64) any0 |= c0[k];
            any0 = __any_sync(0xffffffffu, any0 != 0);
            if (lane == 0) { g_eisel = any0 ? 1 : 0; g_is64 = 1; }
        } else {
            const int* w = host_eisel ? c1 : c0;
            int any = 0;
            for (int k = 1 + 2 * lane; k < 2048; k += 64) any |= w[k];
            any = __any_sync(0xffffffffu, any != 0);
            if (lane == 0) { g_eisel = host_eisel; g_is64 = any ? 0 : 1; }
        }
    }
}

// ---------------- pass 1: count cols + edge rank (reads col half only) ----------------
__global__ void k_count(const void* __restrict__ c0, const void* __restrict__ c1,
                        int e, int n) {
    int i = blockIdx.x * blockDim.x + threadIdx.x;
    if (i >= e) return;
    const void* p = g_eisel ? c1 : c0;
    int c;
    if (g_is64) c = (int)((const long long*)p)[e + i];
    else        c = ((const int*)p)[e + i];
    if ((unsigned)c >= (unsigned)n) c = 0;
    g_rank[i] = atomicAdd(&g_cnt[c], 1);
}

// ---------------- scan (block-local) + dinv + last-block scans block sums ----------------
__global__ void k_scan1(int n, int nb) {
    __shared__ int s[SCAN_BLK];
    __shared__ int is_last;
    int t = threadIdx.x;
    int i = blockIdx.x * SCAN_BLK + t;
    int v = (i < n) ? g_cnt[i] : 0;
    s[t] = v;
    __syncthreads();
    for (int d = 1; d < SCAN_BLK; d <<= 1) {
        int u = (t >= d) ? s[t - d] : 0;
        __syncthreads();
        s[t] += u;
        __syncthreads();
    }
    if (i < n) {
        g_off[i]  = s[t] - v;                     // block-local exclusive
        g_dinv[i] = rsqrtf((float)v + 1.0f);
    }
    if (t == SCAN_BLK - 1) g_bsum[blockIdx.x] = s[t];   // block total
    // last block to finish scans the block sums (<= 64 of them)
    __threadfence();
    __syncthreads();
    if (t == 0) is_last = (atomicAdd(&g_done, 1) == nb - 1) ? 1 : 0;
    __syncthreads();
    if (is_last) {                                // block-uniform: barriers legal
        int bv = (t < nb) ? g_bsum[t] : 0;
        s[t] = bv;
        __syncthreads();
        if (t == 0) {
            int run = 0;
            for (int k = 0; k < nb; k++) {
                int val = s[k];
                s[k] = run;                        // exclusive
                run += val;
            }
        }
        __syncthreads();
        if (t < nb) g_bsum[t] = s[t];              // exclusive block offsets
        if (t == nb - 1) g_off[n] = bv;            // last block's LOCAL total
    }
}

// ---------------- pass 2: fill row-only CSR (re-decode, no atomics) ----------------
__global__ void k_fill(const void* __restrict__ c0, const void* __restrict__ c1,
                       int e, int n) {
    int i = blockIdx.x * blockDim.x + threadIdx.x;
    if (i >= e) return;
    const void* p = g_eisel ? c1 : c0;
    int r, c;
    if (g_is64) {
        const long long* q = (const long long*)p;
        r = (int)q[i];
        c = (int)q[e + i];
    } else {
        const int* q = (const int*)p;
        r = q[i];
        c = q[e + i];
    }
    if ((unsigned)r >= (unsigned)n) r = 0;
    if ((unsigned)c >= (unsigned)n) c = 0;
    int off = g_off[c] + __ldg(&g_bsum[c >> 10]);
    g_csr_row[off + g_rank[i]] = r;
}

// ---------------- h0' = dinv * (x @ W1), 32 nodes/block, f32x2 FMA ----------------
__global__ void k_gemm1(const float* __restrict__ c0, const float* __restrict__ c1,
                        const float* __restrict__ W1, int n) {
    __shared__ float Ws[F_IN * F_H];       // 32 KB, [k][feat]
    __shared__ float xsT[F_IN][34];        // [k][node], padded
    const float* x = g_eisel ? c0 : c1;
    int tx = threadIdx.x;                  // 0..63 : out feature
    int ty = threadIdx.y;                  // 0..3  : node octet
    int tid = ty * 64 + tx;
    int node0 = blockIdx.x * 32;
    for (int i = tid; i < F_IN * F_H; i += 256) Ws[i] = W1[i];
    for (int idx = tid; idx < 32 * F_IN; idx += 256) {
        int nd = idx >> 7;
        int k  = idx & 127;
        int node = node0 + nd;
        xsT[k][nd] = (node < n) ? x[(size_t)node * F_IN + k] : 0.0f;
    }
    __syncthreads();
    unsigned long long acc[4] = {0ull, 0ull, 0ull, 0ull};
    int nb = ty * 8;
#pragma unroll 8
    for (int k = 0; k < F_IN; k++) {
        float w = Ws[k * F_H + tx];
        unsigned long long w2 = pack2(w, w);
#pragma unroll
        for (int p = 0; p < 4; p++) {
            unsigned long long a2 = *(const unsigned long long*)&xsT[k][nb + 2 * p];
            fma2(acc[p], a2, w2);
        }
    }
    __half* h0 = (__half*)g_h0;
#pragma unroll
    for (int p = 0; p < 4; p++) {
        int n_lo = node0 + nb + 2 * p;
        int n_hi = n_lo + 1;
        if (n_lo < n) h0[n_lo * F_H + tx] = __float2half_rn(lo2(acc[p]) * g_dinv[n_lo]);
        if (n_hi < n) h0[n_hi * F_H + tx] = __float2half_rn(hi2(acc[p]) * g_dinv[n_hi]);
    }
}

// ---------------- gather1: h' = dinv * relu(dinv*(sum h0') + b) ----------------
// lane holds features (2*lane, 2*lane+1)
__global__ void k_gather1(const float* __restrict__ bias, int n) {
    int warp = (blockIdx.x * blockDim.x + threadIdx.x) >> 5;
    int lane = threadIdx.x & 31;
    if (warp >= n) return;
    float di = g_dinv[warp];
    float2 own = __half22float2(g_h0[warp * 32 + lane]);
    float a0 = own.x, a1 = own.y;
    int s = g_off[warp]     + __ldg(&g_bsum[warp >> 10]);
    int e = g_off[warp + 1] + __ldg(&g_bsum[(warp + 1) >> 10]);
    for (int j = s; j < e; j += 32) {
        int cnt = e - j; if (cnt > 32) cnt = 32;
        int r = (lane < cnt) ? __ldg(&g_csr_row[j + lane]) : 0;
#pragma unroll 4
        for (int t = 0; t < cnt; t++) {
            int rr = __shfl_sync(0xffffffffu, r, t);
            float2 f = __half22float2(__ldg(&g_h0[rr * 32 + lane]));
            a0 += f.x;
            a1 += f.y;
        }
    }
    float2 b = ((const float2*)bias)[lane];   // bias features (2*lane, 2*lane+1)
    a0 = fmaxf(fmaf(a0, di, b.x), 0.0f);
    a1 = fmaxf(fmaf(a1, di, b.y), 0.0f);
    g_h[warp * 32 + lane] = __floats2half2_rn(a0 * di, a1 * di);
}

// ---------------- gather2 + output heads (fused, grid-strided) ----------------
__global__ void k_g2out(const float* __restrict__ Wmu, const float* __restrict__ bmu,
                        const float* __restrict__ Wls, const float* __restrict__ bls,
                        float* __restrict__ out, int n) {
    __shared__ float Wm[F_H * F_OUT];   // 8 KB
    __shared__ float Wl[F_H * F_OUT];   // 8 KB
    int tid = threadIdx.x;
    int lane = tid & 31;
    for (int i = tid; i < F_H * F_OUT; i += 256) { Wm[i] = Wmu[i]; Wl[i] = Wls[i]; }
    __syncthreads();
    float bm = bmu[lane], bl = bls[lane];
    int gw = blockIdx.x * 8 + (tid >> 5);
    int stride = gridDim.x * 8;
    for (int node = gw; node < n; node += stride) {
        float di = g_dinv[node];
        float2 own = __half22float2(g_h[node * 32 + lane]);
        float a0 = own.x, a1 = own.y;    // features 2*lane, 2*lane+1
        int s = g_off[node]     + __ldg(&g_bsum[node >> 10]);
        int e = g_off[node + 1] + __ldg(&g_bsum[(node + 1) >> 10]);
        for (int j = s; j < e; j += 32) {
            int cnt = e - j; if (cnt > 32) cnt = 32;
            int r = (lane < cnt) ? __ldg(&g_csr_row[j + lane]) : 0;
#pragma unroll 4
            for (int t = 0; t < cnt; t++) {
                int rr = __shfl_sync(0xffffffffu, r, t);
                float2 f = __half22float2(__ldg(&g_h[rr * 32 + lane]));
                a0 += f.x;
                a1 += f.y;
            }
        }
        a0 *= di;   // g feature 2*lane
        a1 *= di;   // g feature 2*lane+1
        float mu = 0.0f, ls = 0.0f;
#pragma unroll
        for (int k = 0; k < 32; k++) {
            float gx = __shfl_sync(0xffffffffu, a0, k);   // feature 2k
            float gy = __shfl_sync(0xffffffffu, a1, k);   // feature 2k+1
            mu = fmaf(gx, Wm[(2 * k)     * F_OUT + lane], mu);
            mu = fmaf(gy, Wm[(2 * k + 1) * F_OUT + lane], mu);
            ls = fmaf(gx, Wl[(2 * k)     * F_OUT + lane], ls);
            ls = fmaf(gy, Wl[(2 * k + 1) * F_OUT + lane], ls);
        }
        out[(size_t)node * F_OUT + lane]                        = mu + bm;
        out[(size_t)n * F_OUT + (size_t)node * F_OUT + lane]    = ls + bl;
    }
}

// ---------------- launch ----------------
extern "C" void kernel_launch(void* const* d_in, const int* in_sizes, int n_in,
                              void* d_out, int out_size) {
    int n = out_size / (2 * F_OUT);

    long long best1 = -1, best2 = -1; int i1 = -1, i2 = -1;
    for (int i = 0; i < n_in; i++) {
        long long s = in_sizes[i];
        if (s > best1) { best2 = best1; i2 = i1; best1 = s; i1 = i; }
        else if (s > best2) { best2 = s; i2 = i; }
    }
    int tie = (best1 == best2);

    int idx_W1 = -1, idx_b1 = -1;
    int idx_W_a = -1, idx_W_b = -1, idx_b_a = -1, idx_b_b = -1;
    for (int i = 0; i < n_in; i++) {
        if (i == i1 || i == i2) continue;
        int s = in_sizes[i];
        if (s == F_IN * F_H) idx_W1 = i;
        else if (s == F_H) idx_b1 = i;
        else if (s == F_H * F_OUT) { if (idx_W_a < 0) idx_W_a = i; else idx_W_b = i; }
        else if (s == F_OUT) { if (idx_b_a < 0) idx_b_a = i; else idx_b_b = i; }
    }
    int min_big = (i1 < i2) ? i1 : i2;
    int mu_first = (min_big == 0) ? 1 : 0;
    int idx_Wmu = mu_first ? idx_W_a : idx_W_b;
    int idx_Wls = mu_first ? idx_W_b : idx_W_a;
    int idx_bmu = mu_first ? idx_b_a : idx_b_b;
    int idx_bls = mu_first ? idx_b_b : idx_b_a;

    int ca = (i1 < i2) ? i1 : i2;
    int cb = (i1 < i2) ? i2 : i1;
    const float* c0 = (const float*)d_in[ca];
    const float* c1 = (const float*)d_in[cb];

    int e, host_eisel = 0;
    if (tie) {
        e = in_sizes[ca] / 4;
        if (n <= 0) n = in_sizes[ca] / F_IN;
    } else {
        int idx_x  = (in_sizes[ca] > in_sizes[cb]) ? ca : cb;
        int idx_ei = (idx_x == ca) ? cb : ca;
        e = in_sizes[idx_ei] / 2;
        host_eisel = (idx_ei == cb) ? 1 : 0;
        if (n <= 0) n = in_sizes[idx_x] / F_IN;
    }
    if (n > N_NODES) n = N_NODES;
    if (e > N_EDGES) e = N_EDGES;

    const float* W1  = (const float*)d_in[idx_W1];
    const float* b1  = (const float*)d_in[idx_b1];
    const float* Wmu = (const float*)d_in[idx_Wmu];
    const float* bmu = (const float*)d_in[idx_bmu];
    const float* Wls = (const float*)d_in[idx_Wls];
    const float* bls = (const float*)d_in[idx_bls];
    float* out = (float*)d_out;

    int nb = (n + SCAN_BLK - 1) / SCAN_BLK;

    k_zero_probe<<<(n + 255) / 256, 256>>>((const int*)c0, (const int*)c1, tie, host_eisel, n);
    k_count     <<<(e + 255) / 256, 256>>>((const void*)c0, (const void*)c1, e, n);
    k_scan1     <<<nb, SCAN_BLK>>>(n, nb);
    k_fill      <<<(e + 255) / 256, 256>>>((const void*)c0, (const void*)c1, e, n);

    k_gemm1<<<(n + 31) / 32, dim3(64, 4)>>>(c0, c1, W1, n);

    k_gather1<<<(n + 7) / 8, 256>>>(b1, n);
    k_g2out  <<<1184, 256>>>(Wmu, bmu, Wls, bls, out, n);
}

// round 13
// speedup vs baseline: 1.9420x; 1.0258x over previous
#include <cuda_runtime.h>
#include <cuda_fp16.h>
#include <stdint.h>

#define N_NODES 50000
#define N_EDGES 1600000
#define F_IN 128
#define F_H  64
#define F_OUT 32
#define SCAN_BLK 1024

// ---------------- device scratch (no allocations allowed) ----------------
__device__ int     g_is64;
__device__ int     g_eisel;
__device__ int     g_done;                    // scan1 completion counter
__device__ int     g_rank[N_EDGES];           // per-edge rank within its col
__device__ int     g_cnt[N_NODES];
__device__ int     g_off[N_NODES + 1];        // block-LOCAL exclusive offsets
__device__ int     g_bsum[64];                // exclusive block offsets (after scan1)
__device__ float   g_dinv[N_NODES];
__device__ int     g_csr_row[N_EDGES];        // row indices only (norm folded out)
__device__ __half2 g_h0[N_NODES * (F_H / 2)]; // dinv * (x @ W1)      (pre-scaled fp16)
__device__ __half2 g_h [N_NODES * (F_H / 2)]; // dinv * relu(layer1)  (pre-scaled fp16)

// packed fp32x2 FMA (Blackwell FFMA2) helpers
__device__ __forceinline__ unsigned long long pack2(float lo, float hi) {
    unsigned long long r;
    asm("mov.b64 %0, {%1, %2};" : "=l"(r) : "r"(__float_as_uint(lo)), "r"(__float_as_uint(hi)));
    return r;
}
__device__ __forceinline__ void fma2(unsigned long long& acc, unsigned long long a,
                                     unsigned long long b) {
    asm("fma.rn.f32x2 %0, %1, %2, %0;" : "+l"(acc) : "l"(a), "l"(b));
}
__device__ __forceinline__ float lo2(unsigned long long v) {
    return __uint_as_float((unsigned)(v & 0xFFFFFFFFull));
}
__device__ __forceinline__ float hi2(unsigned long long v) {
    return __uint_as_float((unsigned)(v >> 32));
}

// ---------------- zero + probe (fused, warp-parallel probe) ----------------
__global__ void k_zero_probe(const int* __restrict__ c0, const int* __restrict__ c1,
                             int tie, int host_eisel, int n) {
    int i = blockIdx.x * blockDim.x + threadIdx.x;
    if (i < n) g_cnt[i] = 0;
    if (blockIdx.x == 0 && threadIdx.x < 32) {
        int lane = threadIdx.x;
        if (lane == 0) g_done = 0;
        if (tie) {
            int any0 = 0;
            for (int k = 1 + 2 * lane; k < 2048; k += 64) any0 |= c0[k];
            any0 = __any_sync(0xffffffffu, any0 != 0);
            if (lane == 0) { g_eisel = any0 ? 1 : 0; g_is64 = 1; }
        } else {
            const int* w = host_eisel ? c1 : c0;
            int any = 0;
            for (int k = 1 + 2 * lane; k < 2048; k += 64) any |= w[k];
            any = __any_sync(0xffffffffu, any != 0);
            if (lane == 0) { g_eisel = host_eisel; g_is64 = any ? 0 : 1; }
        }
    }
}

// ---------------- pass 1: count cols + edge rank (reads col half only) ----------------
__global__ void k_count(const void* __restrict__ c0, const void* __restrict__ c1,
                        int e, int n) {
    int i = blockIdx.x * blockDim.x + threadIdx.x;
    if (i >= e) return;
    const void* p = g_eisel ? c1 : c0;
    int c;
    if (g_is64) c = (int)((const long long*)p)[e + i];
    else        c = ((const int*)p)[e + i];
    if ((unsigned)c >= (unsigned)n) c = 0;
    g_rank[i] = atomicAdd(&g_cnt[c], 1);
}

// ---------------- scan (block-local) + dinv + last-block scans block sums ----------------
__global__ void k_scan1(int n, int nb) {
    __shared__ int s[SCAN_BLK];
    __shared__ int is_last;
    int t = threadIdx.x;
    int i = blockIdx.x * SCAN_BLK + t;
    int v = (i < n) ? g_cnt[i] : 0;
    s[t] = v;
    __syncthreads();
    for (int d = 1; d < SCAN_BLK; d <<= 1) {
        int u = (t >= d) ? s[t - d] : 0;
        __syncthreads();
        s[t] += u;
        __syncthreads();
    }
    if (i < n) {
        g_off[i]  = s[t] - v;                     // block-local exclusive
        g_dinv[i] = rsqrtf((float)v + 1.0f);
    }
    if (t == SCAN_BLK - 1) g_bsum[blockIdx.x] = s[t];   // block total
    __threadfence();
    __syncthreads();
    if (t == 0) is_last = (atomicAdd(&g_done, 1) == nb - 1) ? 1 : 0;
    __syncthreads();
    if (is_last) {                                // block-uniform: barriers legal
        int bv = (t < nb) ? g_bsum[t] : 0;
        s[t] = bv;
        __syncthreads();
        if (t == 0) {
            int run = 0;
            for (int k = 0; k < nb; k++) {
                int val = s[k];
                s[k] = run;                        // exclusive
                run += val;
            }
        }
        __syncthreads();
        if (t < nb) g_bsum[t] = s[t];              // exclusive block offsets
        if (t == nb - 1) g_off[n] = bv;            // last block's LOCAL total
    }
}

// ---------------- pass 2: fill row-only CSR (re-decode, no atomics) ----------------
__global__ void k_fill(const void* __restrict__ c0, const void* __restrict__ c1,
                       int e, int n) {
    int i = blockIdx.x * blockDim.x + threadIdx.x;
    if (i >= e) return;
    const void* p = g_eisel ? c1 : c0;
    int r, c;
    if (g_is64) {
        const long long* q = (const long long*)p;
        r = (int)q[i];
        c = (int)q[e + i];
    } else {
        const int* q = (const int*)p;
        r = q[i];
        c = q[e + i];
    }
    if ((unsigned)r >= (unsigned)n) r = 0;
    if ((unsigned)c >= (unsigned)n) c = 0;
    int off = g_off[c] + __ldg(&g_bsum[c >> 10]);
    g_csr_row[off + g_rank[i]] = r;
}

// ---------------- h0' = dinv * (x @ W1), 32 nodes/block, f32x2 FMA ----------------
__global__ void k_gemm1(const float* __restrict__ c0, const float* __restrict__ c1,
                        const float* __restrict__ W1, int n) {
    __shared__ float Ws[F_IN * F_H];       // 32 KB, [k][feat]
    __shared__ float xsT[F_IN][34];        // [k][node], padded
    const float* x = g_eisel ? c0 : c1;
    int tx = threadIdx.x;                  // 0..63 : out feature
    int ty = threadIdx.y;                  // 0..3  : node octet
    int tid = ty * 64 + tx;
    int node0 = blockIdx.x * 32;
    for (int i = tid; i < F_IN * F_H; i += 256) Ws[i] = W1[i];
    for (int idx = tid; idx < 32 * F_IN; idx += 256) {
        int nd = idx >> 7;
        int k  = idx & 127;
        int node = node0 + nd;
        xsT[k][nd] = (node < n) ? x[(size_t)node * F_IN + k] : 0.0f;
    }
    __syncthreads();
    unsigned long long acc[4] = {0ull, 0ull, 0ull, 0ull};
    int nb = ty * 8;
#pragma unroll 8
    for (int k = 0; k < F_IN; k++) {
        float w = Ws[k * F_H + tx];
        unsigned long long w2 = pack2(w, w);
#pragma unroll
        for (int p = 0; p < 4; p++) {
            unsigned long long a2 = *(const unsigned long long*)&xsT[k][nb + 2 * p];
            fma2(acc[p], a2, w2);
        }
    }
    __half* h0 = (__half*)g_h0;
#pragma unroll
    for (int p = 0; p < 4; p++) {
        int n_lo = node0 + nb + 2 * p;
        int n_hi = n_lo + 1;
        if (n_lo < n) h0[n_lo * F_H + tx] = __float2half_rn(lo2(acc[p]) * g_dinv[n_lo]);
        if (n_hi < n) h0[n_hi * F_H + tx] = __float2half_rn(hi2(acc[p]) * g_dinv[n_hi]);
    }
}

// ---------------- gather1: h' = dinv * relu(dinv*(sum h0') + b) ----------------
// lane holds features (2*lane, 2*lane+1)
__global__ void k_gather1(const float* __restrict__ bias, int n) {
    int warp = (blockIdx.x * blockDim.x + threadIdx.x) >> 5;
    int lane = threadIdx.x & 31;
    if (warp >= n) return;
    float di = g_dinv[warp];
    float2 own = __half22float2(g_h0[warp * 32 + lane]);
    float a0 = own.x, a1 = own.y;
    int s = g_off[warp]     + __ldg(&g_bsum[warp >> 10]);
    int e = g_off[warp + 1] + __ldg(&g_bsum[(warp + 1) >> 10]);
    for (int j = s; j < e; j += 32) {
        int cnt = e - j; if (cnt > 32) cnt = 32;
        int r = (lane < cnt) ? __ldg(&g_csr_row[j + lane]) : 0;
#pragma unroll 4
        for (int t = 0; t < cnt; t++) {
            int rr = __shfl_sync(0xffffffffu, r, t);
            float2 f = __half22float2(__ldg(&g_h0[rr * 32 + lane]));
            a0 += f.x;
            a1 += f.y;
        }
    }
    float2 b = ((const float2*)bias)[lane];   // bias features (2*lane, 2*lane+1)
    a0 = fmaxf(fmaf(a0, di, b.x), 0.0f);
    a1 = fmaxf(fmaf(a1, di, b.y), 0.0f);
    g_h[warp * 32 + lane] = __floats2half2_rn(a0 * di, a1 * di);
}

// ---------------- gather2 + output heads (fused, grid-strided) ----------------
__global__ void k_g2out(const float* __restrict__ Wmu, const float* __restrict__ bmu,
                        const float* __restrict__ Wls, const float* __restrict__ bls,
                        float* __restrict__ out, int n) {
    __shared__ float Wm[F_H * F_OUT];   // 8 KB
    __shared__ float Wl[F_H * F_OUT];   // 8 KB
    int tid = threadIdx.x;
    int lane = tid & 31;
    for (int i = tid; i < F_H * F_OUT; i += 256) { Wm[i] = Wmu[i]; Wl[i] = Wls[i]; }
    __syncthreads();
    float bm = bmu[lane], bl = bls[lane];
    int gw = blockIdx.x * 8 + (tid >> 5);
    int stride = gridDim.x * 8;
    for (int node = gw; node < n; node += stride) {
        float di = g_dinv[node];
        float2 own = __half22float2(g_h[node * 32 + lane]);
        float a0 = own.x, a1 = own.y;    // features 2*lane, 2*lane+1
        int s = g_off[node]     + __ldg(&g_bsum[node >> 10]);
        int e = g_off[node + 1] + __ldg(&g_bsum[(node + 1) >> 10]);
        for (int j = s; j < e; j += 32) {
            int cnt = e - j; if (cnt > 32) cnt = 32;
            int r = (lane < cnt) ? __ldg(&g_csr_row[j + lane]) : 0;
#pragma unroll 4
            for (int t = 0; t < cnt; t++) {
                int rr = __shfl_sync(0xffffffffu, r, t);
                float2 f = __half22float2(__ldg(&g_h[rr * 32 + lane]));
                a0 += f.x;
                a1 += f.y;
            }
        }
        a0 *= di;   // g feature 2*lane
        a1 *= di;   // g feature 2*lane+1
        float mu = 0.0f, ls = 0.0f;
#pragma unroll
        for (int k = 0; k < 32; k++) {
            float gx = __shfl_sync(0xffffffffu, a0, k);   // feature 2k
            float gy = __shfl_sync(0xffffffffu, a1, k);   // feature 2k+1
            mu = fmaf(gx, Wm[(2 * k)     * F_OUT + lane], mu);
            mu = fmaf(gy, Wm[(2 * k + 1) * F_OUT + lane], mu);
            ls = fmaf(gx, Wl[(2 * k)     * F_OUT + lane], ls);
            ls = fmaf(gy, Wl[(2 * k + 1) * F_OUT + lane], ls);
        }
        out[(size_t)node * F_OUT + lane]                        = mu + bm;
        out[(size_t)n * F_OUT + (size_t)node * F_OUT + lane]    = ls + bl;
    }
}

// ---------------- launch ----------------
extern "C" void kernel_launch(void* const* d_in, const int* in_sizes, int n_in,
                              void* d_out, int out_size) {
    int n = out_size / (2 * F_OUT);

    long long best1 = -1, best2 = -1; int i1 = -1, i2 = -1;
    for (int i = 0; i < n_in; i++) {
        long long s = in_sizes[i];
        if (s > best1) { best2 = best1; i2 = i1; best1 = s; i1 = i; }
        else if (s > best2) { best2 = s; i2 = i; }
    }
    int tie = (best1 == best2);

    int idx_W1 = -1, idx_b1 = -1;
    int idx_W_a = -1, idx_W_b = -1, idx_b_a = -1, idx_b_b = -1;
    for (int i = 0; i < n_in; i++) {
        if (i == i1 || i == i2) continue;
        int s = in_sizes[i];
        if (s == F_IN * F_H) idx_W1 = i;
        else if (s == F_H) idx_b1 = i;
        else if (s == F_H * F_OUT) { if (idx_W_a < 0) idx_W_a = i; else idx_W_b = i; }
        else if (s == F_OUT) { if (idx_b_a < 0) idx_b_a = i; else idx_b_b = i; }
    }
    int min_big = (i1 < i2) ? i1 : i2;
    int mu_first = (min_big == 0) ? 1 : 0;
    int idx_Wmu = mu_first ? idx_W_a : idx_W_b;
    int idx_Wls = mu_first ? idx_W_b : idx_W_a;
    int idx_bmu = mu_first ? idx_b_a : idx_b_b;
    int idx_bls = mu_first ? idx_b_b : idx_b_a;

    int ca = (i1 < i2) ? i1 : i2;
    int cb = (i1 < i2) ? i2 : i1;
    const float* c0 = (const float*)d_in[ca];
    const float* c1 = (const float*)d_in[cb];

    int e, host_eisel = 0;
    if (tie) {
        e = in_sizes[ca] / 4;
        if (n <= 0) n = in_sizes[ca] / F_IN;
    } else {
        int idx_x  = (in_sizes[ca] > in_sizes[cb]) ? ca : cb;
        int idx_ei = (idx_x == ca) ? cb : ca;
        e = in_sizes[idx_ei] / 2;
        host_eisel = (idx_ei == cb) ? 1 : 0;
        if (n <= 0) n = in_sizes[idx_x] / F_IN;
    }
    if (n > N_NODES) n = N_NODES;
    if (e > N_EDGES) e = N_EDGES;

    const float* W1  = (const float*)d_in[idx_W1];
    const float* b1  = (const float*)d_in[idx_b1];
    const float* Wmu = (const float*)d_in[idx_Wmu];
    const float* bmu = (const float*)d_in[idx_bmu];
    const float* Wls = (const float*)d_in[idx_Wls];
    const float* bls = (const float*)d_in[idx_bls];
    float* out = (float*)d_out;

    // fork-join side stream (created once on first, non-captured, call)
    static cudaStream_t s2 = nullptr;
    static cudaEvent_t ev_fork = nullptr, ev_join = nullptr;
    if (s2 == nullptr) {
        cudaStreamCreateWithFlags(&s2, cudaStreamNonBlocking);
        cudaEventCreateWithFlags(&ev_fork, cudaEventDisableTiming);
        cudaEventCreateWithFlags(&ev_join, cudaEventDisableTiming);
    }

    int nb = (n + SCAN_BLK - 1) / SCAN_BLK;

    k_zero_probe<<<(n + 255) / 256, 256>>>((const int*)c0, (const int*)c1, tie, host_eisel, n);
    k_count     <<<(e + 255) / 256, 256>>>((const void*)c0, (const void*)c1, e, n);
    k_scan1     <<<nb, SCAN_BLK>>>(n, nb);

    // fork: gemm1 (independent of CSR fill) runs on side stream
    cudaEventRecord(ev_fork, 0);
    cudaStreamWaitEvent(s2, ev_fork, 0);
    k_gemm1<<<(n + 31) / 32, dim3(64, 4), 0, s2>>>(c0, c1, W1, n);
    k_fill <<<(e + 255) / 256, 256>>>((const void*)c0, (const void*)c1, e, n);
    // join
    cudaEventRecord(ev_join, s2);
    cudaStreamWaitEvent(0, ev_join, 0);

    k_gather1<<<(n + 7) / 8, 256>>>(b1, n);
    k_g2out  <<<1184, 256>>>(Wmu, bmu, Wls, bls, out, n);
}

// round 14
// speedup vs baseline: 2.0111x; 1.0356x over previous
#include <cuda_runtime.h>
#include <cuda_fp16.h>
#include <stdint.h>

#define N_NODES 50000
#define N_EDGES 1600000
#define F_IN 128
#define F_H  64
#define F_OUT 32
#define SCAN_BLK 1024

// ---------------- device scratch (no allocations allowed) ----------------
__device__ int     g_is64;
__device__ int     g_eisel;
__device__ int     g_done;                    // scan1 completion counter
__device__ int     g_rank[N_EDGES];           // per-edge rank within its col
__device__ int     g_cnt[N_NODES];
__device__ int     g_off[N_NODES + 1];        // block-LOCAL exclusive offsets
__device__ int     g_bsum[64];                // exclusive block offsets (after scan1)
__device__ float   g_dinv[N_NODES];
__device__ int     g_csr_row[N_EDGES];        // row indices only (norm folded out)
__device__ __half2 g_h0[N_NODES * (F_H / 2)]; // dinv * (x @ W1)      (pre-scaled fp16)
__device__ __half2 g_h [N_NODES * (F_H / 2)]; // dinv * relu(layer1)  (pre-scaled fp16)

// packed fp32x2 FMA (Blackwell FFMA2) helpers
__device__ __forceinline__ unsigned long long pack2(float lo, float hi) {
    unsigned long long r;
    asm("mov.b64 %0, {%1, %2};" : "=l"(r) : "r"(__float_as_uint(lo)), "r"(__float_as_uint(hi)));
    return r;
}
__device__ __forceinline__ void fma2(unsigned long long& acc, unsigned long long a,
                                     unsigned long long b) {
    asm("fma.rn.f32x2 %0, %1, %2, %0;" : "+l"(acc) : "l"(a), "l"(b));
}
__device__ __forceinline__ float lo2(unsigned long long v) {
    return __uint_as_float((unsigned)(v & 0xFFFFFFFFull));
}
__device__ __forceinline__ float hi2(unsigned long long v) {
    return __uint_as_float((unsigned)(v >> 32));
}

// ---------------- zero + probe (fused, warp-parallel probe) ----------------
__global__ void k_zero_probe(const int* __restrict__ c0, const int* __restrict__ c1,
                             int tie, int host_eisel, int n) {
    int i = blockIdx.x * blockDim.x + threadIdx.x;
    if (i < n) g_cnt[i] = 0;
    if (blockIdx.x == 0 && threadIdx.x < 32) {
        int lane = threadIdx.x;
        if (lane == 0) g_done = 0;
        if (tie) {
            int any0 = 0;
            for (int k = 1 + 2 * lane; k < 2048; k += 64) any0 |= c0[k];
            any0 = __any_sync(0xffffffffu, any0 != 0);
            if (lane == 0) { g_eisel = any0 ? 1 : 0; g_is64 = 1; }
        } else {
            const int* w = host_eisel ? c1 : c0;
            int any = 0;
            for (int k = 1 + 2 * lane; k < 2048; k += 64) any |= w[k];
            any = __any_sync(0xffffffffu, any != 0);
            if (lane == 0) { g_eisel = host_eisel; g_is64 = any ? 0 : 1; }
        }
    }
}

// ---------------- pass 1: count cols + edge rank (reads col half only) ----------------
__global__ void k_count(const void* __restrict__ c0, const void* __restrict__ c1,
                        int e, int n) {
    int i = blockIdx.x * blockDim.x + threadIdx.x;
    if (i >= e) return;
    const void* p = g_eisel ? c1 : c0;
    int c;
    if (g_is64) c = (int)((const long long*)p)[e + i];
    else        c = ((const int*)p)[e + i];
    if ((unsigned)c >= (unsigned)n) c = 0;
    g_rank[i] = atomicAdd(&g_cnt[c], 1);
}

// ---------------- scan (block-local) + dinv + last-block scans block sums ----------------
__global__ void k_scan1(int n, int nb) {
    __shared__ int s[SCAN_BLK];
    __shared__ int is_last;
    int t = threadIdx.x;
    int i = blockIdx.x * SCAN_BLK + t;
    int v = (i < n) ? g_cnt[i] : 0;
    s[t] = v;
    __syncthreads();
    for (int d = 1; d < SCAN_BLK; d <<= 1) {
        int u = (t >= d) ? s[t - d] : 0;
        __syncthreads();
        s[t] += u;
        __syncthreads();
    }
    if (i < n) {
        g_off[i]  = s[t] - v;                     // block-local exclusive
        g_dinv[i] = rsqrtf((float)v + 1.0f);
    }
    if (t == SCAN_BLK - 1) g_bsum[blockIdx.x] = s[t];   // block total
    __threadfence();
    __syncthreads();
    if (t == 0) is_last = (atomicAdd(&g_done, 1) == nb - 1) ? 1 : 0;
    __syncthreads();
    if (is_last) {                                // block-uniform: barriers legal
        int bv = (t < nb) ? g_bsum[t] : 0;
        s[t] = bv;
        __syncthreads();
        if (t == 0) {
            int run = 0;
            for (int k = 0; k < nb; k++) {
                int val = s[k];
                s[k] = run;                        // exclusive
                run += val;
            }
        }
        __syncthreads();
        if (t < nb) g_bsum[t] = s[t];              // exclusive block offsets
        if (t == nb - 1) g_off[n] = bv;            // last block's LOCAL total
    }
}

// ---------------- pass 2: fill row-only CSR (re-decode, no atomics) ----------------
__global__ void k_fill(const void* __restrict__ c0, const void* __restrict__ c1,
                       int e, int n) {
    int i = blockIdx.x * blockDim.x + threadIdx.x;
    if (i >= e) return;
    const void* p = g_eisel ? c1 : c0;
    int r, c;
    if (g_is64) {
        const long long* q = (const long long*)p;
        r = (int)q[i];
        c = (int)q[e + i];
    } else {
        const int* q = (const int*)p;
        r = q[i];
        c = q[e + i];
    }
    if ((unsigned)r >= (unsigned)n) r = 0;
    if ((unsigned)c >= (unsigned)n) c = 0;
    int off = g_off[c] + __ldg(&g_bsum[c >> 10]);
    g_csr_row[off + g_rank[i]] = r;
}

// ---------------- h0' = dinv*(x@W1): 64 nodes/block, 16 nodes/thread ----------------
// W1 streamed via LDG (L1-resident); x transposed in smem; LDS.128 broadcasts.
__global__ void k_gemm1(const float* __restrict__ c0, const float* __restrict__ c1,
                        const float* __restrict__ W1, int n) {
    __shared__ __align__(16) float xsT[F_IN][68];   // [k][node], 16B-aligned rows (68*4=272=16*17)
    const float* x = g_eisel ? c0 : c1;
    int tx = threadIdx.x;                  // 0..63 : out feature
    int ty = threadIdx.y;                  // 0..3  : node group of 16
    int tid = ty * 64 + tx;
    int node0 = blockIdx.x * 64;
    for (int idx = tid; idx < 64 * F_IN; idx += 256) {
        int nd = idx >> 7;                 // node within block (0..63)
        int k  = idx & 127;
        int node = node0 + nd;
        xsT[k][nd] = (node < n) ? x[(size_t)node * F_IN + k] : 0.0f;
    }
    __syncthreads();
    unsigned long long acc[8] = {0ull,0ull,0ull,0ull,0ull,0ull,0ull,0ull};
    int nb = ty * 16;
#pragma unroll 4
    for (int k = 0; k < F_IN; k++) {
        float w = __ldg(&W1[k * F_H + tx]);
        unsigned long long w2 = pack2(w, w);
#pragma unroll
        for (int p = 0; p < 4; p++) {
            ulonglong2 v = *(const ulonglong2*)&xsT[k][nb + 4 * p];
            fma2(acc[2 * p],     v.x, w2);
            fma2(acc[2 * p + 1], v.y, w2);
        }
    }
    __half* h0 = (__half*)g_h0;
#pragma unroll
    for (int j = 0; j < 8; j++) {
        int n_lo = node0 + nb + 2 * j;
        int n_hi = n_lo + 1;
        if (n_lo < n) h0[n_lo * F_H + tx] = __float2half_rn(lo2(acc[j]) * g_dinv[n_lo]);
        if (n_hi < n) h0[n_hi * F_H + tx] = __float2half_rn(hi2(acc[j]) * g_dinv[n_hi]);
    }
}

// ---------------- gather1: h' = dinv * relu(dinv*(sum h0') + b) ----------------
// lane holds features (2*lane, 2*lane+1)
__global__ void k_gather1(const float* __restrict__ bias, int n) {
    int warp = (blockIdx.x * blockDim.x + threadIdx.x) >> 5;
    int lane = threadIdx.x & 31;
    if (warp >= n) return;
    float di = g_dinv[warp];
    float2 own = __half22float2(g_h0[warp * 32 + lane]);
    float a0 = own.x, a1 = own.y;
    int s = g_off[warp]     + __ldg(&g_bsum[warp >> 10]);
    int e = g_off[warp + 1] + __ldg(&g_bsum[(warp + 1) >> 10]);
    for (int j = s; j < e; j += 32) {
        int cnt = e - j; if (cnt > 32) cnt = 32;
        int r = (lane < cnt) ? __ldg(&g_csr_row[j + lane]) : 0;
#pragma unroll 4
        for (int t = 0; t < cnt; t++) {
            int rr = __shfl_sync(0xffffffffu, r, t);
            float2 f = __half22float2(__ldg(&g_h0[rr * 32 + lane]));
            a0 += f.x;
            a1 += f.y;
        }
    }
    float2 b = ((const float2*)bias)[lane];   // bias features (2*lane, 2*lane+1)
    a0 = fmaxf(fmaf(a0, di, b.x), 0.0f);
    a1 = fmaxf(fmaf(a1, di, b.y), 0.0f);
    g_h[warp * 32 + lane] = __floats2half2_rn(a0 * di, a1 * di);
}

// ---------------- gather2 + output heads (fused, grid-strided) ----------------
__global__ void k_g2out(const float* __restrict__ Wmu, const float* __restrict__ bmu,
                        const float* __restrict__ Wls, const float* __restrict__ bls,
                        float* __restrict__ out, int n) {
    __shared__ float Wm[F_H * F_OUT];   // 8 KB
    __shared__ float Wl[F_H * F_OUT];   // 8 KB
    int tid = threadIdx.x;
    int lane = tid & 31;
    for (int i = tid; i < F_H * F_OUT; i += 256) { Wm[i] = Wmu[i]; Wl[i] = Wls[i]; }
    __syncthreads();
    float bm = bmu[lane], bl = bls[lane];
    int gw = blockIdx.x * 8 + (tid >> 5);
    int stride = gridDim.x * 8;
    for (int node = gw; node < n; node += stride) {
        float di = g_dinv[node];
        float2 own = __half22float2(g_h[node * 32 + lane]);
        float a0 = own.x, a1 = own.y;    // features 2*lane, 2*lane+1
        int s = g_off[node]     + __ldg(&g_bsum[node >> 10]);
        int e = g_off[node + 1] + __ldg(&g_bsum[(node + 1) >> 10]);
        for (int j = s; j < e; j += 32) {
            int cnt = e - j; if (cnt > 32) cnt = 32;
            int r = (lane < cnt) ? __ldg(&g_csr_row[j + lane]) : 0;
#pragma unroll 4
            for (int t = 0; t < cnt; t++) {
                int rr = __shfl_sync(0xffffffffu, r, t);
                float2 f = __half22float2(__ldg(&g_h[rr * 32 + lane]));
                a0 += f.x;
                a1 += f.y;
            }
        }
        a0 *= di;   // g feature 2*lane
        a1 *= di;   // g feature 2*lane+1
        float mu = 0.0f, ls = 0.0f;
#pragma unroll
        for (int k = 0; k < 32; k++) {
            float gx = __shfl_sync(0xffffffffu, a0, k);   // feature 2k
            float gy = __shfl_sync(0xffffffffu, a1, k);   // feature 2k+1
            mu = fmaf(gx, Wm[(2 * k)     * F_OUT + lane], mu);
            mu = fmaf(gy, Wm[(2 * k + 1) * F_OUT + lane], mu);
            ls = fmaf(gx, Wl[(2 * k)     * F_OUT + lane], ls);
            ls = fmaf(gy, Wl[(2 * k + 1) * F_OUT + lane], ls);
        }
        out[(size_t)node * F_OUT + lane]                        = mu + bm;
        out[(size_t)n * F_OUT + (size_t)node * F_OUT + lane]    = ls + bl;
    }
}

// ---------------- launch ----------------
extern "C" void kernel_launch(void* const* d_in, const int* in_sizes, int n_in,
                              void* d_out, int out_size) {
    int n = out_size / (2 * F_OUT);

    long long best1 = -1, best2 = -1; int i1 = -1, i2 = -1;
    for (int i = 0; i < n_in; i++) {
        long long s = in_sizes[i];
        if (s > best1) { best2 = best1; i2 = i1; best1 = s; i1 = i; }
        else if (s > best2) { best2 = s; i2 = i; }
    }
    int tie = (best1 == best2);

    int idx_W1 = -1, idx_b1 = -1;
    int idx_W_a = -1, idx_W_b = -1, idx_b_a = -1, idx_b_b = -1;
    for (int i = 0; i < n_in; i++) {
        if (i == i1 || i == i2) continue;
        int s = in_sizes[i];
        if (s == F_IN * F_H) idx_W1 = i;
        else if (s == F_H) idx_b1 = i;
        else if (s == F_H * F_OUT) { if (idx_W_a < 0) idx_W_a = i; else idx_W_b = i; }
        else if (s == F_OUT) { if (idx_b_a < 0) idx_b_a = i; else idx_b_b = i; }
    }
    int min_big = (i1 < i2) ? i1 : i2;
    int mu_first = (min_big == 0) ? 1 : 0;
    int idx_Wmu = mu_first ? idx_W_a : idx_W_b;
    int idx_Wls = mu_first ? idx_W_b : idx_W_a;
    int idx_bmu = mu_first ? idx_b_a : idx_b_b;
    int idx_bls = mu_first ? idx_b_b : idx_b_a;

    int ca = (i1 < i2) ? i1 : i2;
    int cb = (i1 < i2) ? i2 : i1;
    const float* c0 = (const float*)d_in[ca];
    const float* c1 = (const float*)d_in[cb];

    int e, host_eisel = 0;
    if (tie) {
        e = in_sizes[ca] / 4;
        if (n <= 0) n = in_sizes[ca] / F_IN;
    } else {
        int idx_x  = (in_sizes[ca] > in_sizes[cb]) ? ca : cb;
        int idx_ei = (idx_x == ca) ? cb : ca;
        e = in_sizes[idx_ei] / 2;
        host_eisel = (idx_ei == cb) ? 1 : 0;
        if (n <= 0) n = in_sizes[idx_x] / F_IN;
    }
    if (n > N_NODES) n = N_NODES;
    if (e > N_EDGES) e = N_EDGES;

    const float* W1  = (const float*)d_in[idx_W1];
    const float* b1  = (const float*)d_in[idx_b1];
    const float* Wmu = (const float*)d_in[idx_Wmu];
    const float* bmu = (const float*)d_in[idx_bmu];
    const float* Wls = (const float*)d_in[idx_Wls];
    const float* bls = (const float*)d_in[idx_bls];
    float* out = (float*)d_out;

    // fork-join side stream (created once on first, non-captured, call)
    static cudaStream_t s2 = nullptr;
    static cudaEvent_t ev_fork = nullptr, ev_join = nullptr;
    if (s2 == nullptr) {
        cudaStreamCreateWithFlags(&s2, cudaStreamNonBlocking);
        cudaEventCreateWithFlags(&ev_fork, cudaEventDisableTiming);
        cudaEventCreateWithFlags(&ev_join, cudaEventDisableTiming);
    }

    int nb = (n + SCAN_BLK - 1) / SCAN_BLK;

    k_zero_probe<<<(n + 255) / 256, 256>>>((const int*)c0, (const int*)c1, tie, host_eisel, n);
    k_count     <<<(e + 255) / 256, 256>>>((const void*)c0, (const void*)c1, e, n);
    k_scan1     <<<nb, SCAN_BLK>>>(n, nb);

    // fork: gemm1 (independent of CSR fill) runs on side stream
    cudaEventRecord(ev_fork, 0);
    cudaStreamWaitEvent(s2, ev_fork, 0);
    k_gemm1<<<(n + 63) / 64, dim3(64, 4), 0, s2>>>(c0, c1, W1, n);
    k_fill <<<(e + 255) / 256, 256>>>((const void*)c0, (const void*)c1, e, n);
    // join
    cudaEventRecord(ev_join, s2);
    cudaStreamWaitEvent(0, ev_join, 0);

    k_gather1<<<(n + 7) / 8, 256>>>(b1, n);
    k_g2out  <<<1184, 256>>>(Wmu, bmu, Wls, bls, out, n);
}

// round 15
// speedup vs baseline: 2.1348x; 1.0615x over previous
#include <cuda_runtime.h>
#include <cuda_fp16.h>
#include <stdint.h>

#define N_NODES 50000
#define N_EDGES 1600000
#define F_IN 128
#define F_H  64
#define F_OUT 32
#define SCAN_BLK 1024

// ---------------- device scratch (no allocations allowed) ----------------
__device__ int     g_is64;
__device__ int     g_eisel;
__device__ int     g_done;                    // scan1 completion counter
__device__ int     g_rank[N_EDGES];           // per-edge rank within its col
__device__ int     g_cnt[N_NODES];
__device__ int     g_off[N_NODES + 1];        // block-LOCAL exclusive offsets
__device__ int     g_bsum[64];                // exclusive block offsets (after scan1)
__device__ float   g_dinv[N_NODES];
__device__ int     g_csr_row[N_EDGES];        // row indices only (norm folded out)
__device__ __half2 g_h0[N_NODES * (F_H / 2)]; // dinv * (x @ W1)      (pre-scaled fp16)
__device__ __half2 g_h [N_NODES * (F_H / 2)]; // dinv * relu(layer1)  (pre-scaled fp16)

// packed fp32x2 FMA (Blackwell FFMA2) helpers
__device__ __forceinline__ unsigned long long pack2(float lo, float hi) {
    unsigned long long r;
    asm("mov.b64 %0, {%1, %2};" : "=l"(r) : "r"(__float_as_uint(lo)), "r"(__float_as_uint(hi)));
    return r;
}
__device__ __forceinline__ void fma2(unsigned long long& acc, unsigned long long a,
                                     unsigned long long b) {
    asm("fma.rn.f32x2 %0, %1, %2, %0;" : "+l"(acc) : "l"(a), "l"(b));
}
__device__ __forceinline__ float lo2(unsigned long long v) {
    return __uint_as_float((unsigned)(v & 0xFFFFFFFFull));
}
__device__ __forceinline__ float hi2(unsigned long long v) {
    return __uint_as_float((unsigned)(v >> 32));
}

// ---------------- zero + probe (fused, warp-parallel probe) ----------------
__global__ void k_zero_probe(const int* __restrict__ c0, const int* __restrict__ c1,
                             int tie, int host_eisel, int n) {
    int i = blockIdx.x * blockDim.x + threadIdx.x;
    if (i < n) g_cnt[i] = 0;
    if (blockIdx.x == 0 && threadIdx.x < 32) {
        int lane = threadIdx.x;
        if (lane == 0) g_done = 0;
        if (tie) {
            int any0 = 0;
            for (int k = 1 + 2 * lane; k < 2048; k += 64) any0 |= c0[k];
            any0 = __any_sync(0xffffffffu, any0 != 0);
            if (lane == 0) { g_eisel = any0 ? 1 : 0; g_is64 = 1; }
        } else {
            const int* w = host_eisel ? c1 : c0;
            int any = 0;
            for (int k = 1 + 2 * lane; k < 2048; k += 64) any |= w[k];
            any = __any_sync(0xffffffffu, any != 0);
            if (lane == 0) { g_eisel = host_eisel; g_is64 = any ? 0 : 1; }
        }
    }
}

// ---------------- pass 1: count cols + edge rank (reads col half only) ----------------
__global__ void k_count(const void* __restrict__ c0, const void* __restrict__ c1,
                        int e, int n) {
    int i = blockIdx.x * blockDim.x + threadIdx.x;
    if (i >= e) return;
    const void* p = g_eisel ? c1 : c0;
    int c;
    if (g_is64) c = (int)((const long long*)p)[e + i];
    else        c = ((const int*)p)[e + i];
    if ((unsigned)c >= (unsigned)n) c = 0;
    g_rank[i] = atomicAdd(&g_cnt[c], 1);
}

// ---------------- scan (block-local) + dinv + last-block scans block sums ----------------
__global__ void k_scan1(int n, int nb) {
    __shared__ int s[SCAN_BLK];
    __shared__ int is_last;
    int t = threadIdx.x;
    int i = blockIdx.x * SCAN_BLK + t;
    int v = (i < n) ? g_cnt[i] : 0;
    s[t] = v;
    __syncthreads();
    for (int d = 1; d < SCAN_BLK; d <<= 1) {
        int u = (t >= d) ? s[t - d] : 0;
        __syncthreads();
        s[t] += u;
        __syncthreads();
    }
    if (i < n) {
        g_off[i]  = s[t] - v;                     // block-local exclusive
        g_dinv[i] = rsqrtf((float)v + 1.0f);
    }
    if (t == SCAN_BLK - 1) g_bsum[blockIdx.x] = s[t];   // block total
    __threadfence();
    __syncthreads();
    if (t == 0) is_last = (atomicAdd(&g_done, 1) == nb - 1) ? 1 : 0;
    __syncthreads();
    if (is_last) {                                // block-uniform: barriers legal
        int bv = (t < nb) ? g_bsum[t] : 0;
        s[t] = bv;
        __syncthreads();
        if (t == 0) {
            int run = 0;
            for (int k = 0; k < nb; k++) {
                int val = s[k];
                s[k] = run;                        // exclusive
                run += val;
            }
        }
        __syncthreads();
        if (t < nb) g_bsum[t] = s[t];              // exclusive block offsets
        if (t == nb - 1) g_off[n] = bv;            // last block's LOCAL total
    }
}

// ---------------- pass 2: fill row-only CSR (re-decode, no atomics) ----------------
__global__ void k_fill(const void* __restrict__ c0, const void* __restrict__ c1,
                       int e, int n) {
    int i = blockIdx.x * blockDim.x + threadIdx.x;
    if (i >= e) return;
    const void* p = g_eisel ? c1 : c0;
    int r, c;
    if (g_is64) {
        const long long* q = (const long long*)p;
        r = (int)q[i];
        c = (int)q[e + i];
    } else {
        const int* q = (const int*)p;
        r = q[i];
        c = q[e + i];
    }
    if ((unsigned)r >= (unsigned)n) r = 0;
    if ((unsigned)c >= (unsigned)n) c = 0;
    int off = g_off[c] + __ldg(&g_bsum[c >> 10]);
    g_csr_row[off + g_rank[i]] = r;
}

// ---------------- h0' = dinv*(x@W1): 128 nodes/block, 2 features + 16 nodes/thread ----
// tx (0..31) -> feature pair (2tx, 2tx+1) via one LDG.64 of W1; 4 LDS.128 per k.
__global__ void k_gemm1(const float* __restrict__ c0, const float* __restrict__ c1,
                        const float* __restrict__ W1, int n) {
    __shared__ __align__(16) float xsT[F_IN][132];   // [k][node], 132*4=528=16*33 (16B-aligned rows)
    const float* x = g_eisel ? c0 : c1;
    int tid = threadIdx.x;                 // 256 threads
    int tx = tid & 31;                     // feature pair index (features 2tx, 2tx+1)
    int ty = tid >> 5;                     // 0..7 : node group of 16
    int node0 = blockIdx.x * 128;
    for (int idx = tid; idx < 128 * F_IN; idx += 256) {
        int nd = idx >> 7;                 // node within block (0..127)
        int k  = idx & 127;
        int node = node0 + nd;
        xsT[k][nd] = (node < n) ? x[(size_t)node * F_IN + k] : 0.0f;
    }
    __syncthreads();
    // acc[f][p]: f in {0,1} features, p in 0..7 node-pairs (16 nodes)
    unsigned long long acc0[8] = {0,0,0,0,0,0,0,0};
    unsigned long long acc1[8] = {0,0,0,0,0,0,0,0};
    int nb = ty * 16;
    const float2* Wp = (const float2*)W1;  // Wp[k*32+tx] = (W1[k][2tx], W1[k][2tx+1])
#pragma unroll 4
    for (int k = 0; k < F_IN; k++) {
        float2 w = __ldg(&Wp[k * 32 + tx]);
        unsigned long long w20 = pack2(w.x, w.x);
        unsigned long long w21 = pack2(w.y, w.y);
#pragma unroll
        for (int p = 0; p < 4; p++) {
            ulonglong2 v = *(const ulonglong2*)&xsT[k][nb + 4 * p];
            fma2(acc0[2 * p],     v.x, w20);
            fma2(acc0[2 * p + 1], v.y, w20);
            fma2(acc1[2 * p],     v.x, w21);
            fma2(acc1[2 * p + 1], v.y, w21);
        }
    }
    // store: thread owns half2 word (features 2tx,2tx+1) for its 16 nodes
#pragma unroll
    for (int j = 0; j < 8; j++) {
        int n_lo = node0 + nb + 2 * j;
        int n_hi = n_lo + 1;
        if (n_lo < n) {
            float d = g_dinv[n_lo];
            g_h0[n_lo * 32 + tx] = __floats2half2_rn(lo2(acc0[j]) * d, lo2(acc1[j]) * d);
        }
        if (n_hi < n) {
            float d = g_dinv[n_hi];
            g_h0[n_hi * 32 + tx] = __floats2half2_rn(hi2(acc0[j]) * d, hi2(acc1[j]) * d);
        }
    }
}

// ---------------- gather1: h' = dinv * relu(dinv*(sum h0') + b) ----------------
// lane holds features (2*lane, 2*lane+1)
__global__ void k_gather1(const float* __restrict__ bias, int n) {
    int warp = (blockIdx.x * blockDim.x + threadIdx.x) >> 5;
    int lane = threadIdx.x & 31;
    if (warp >= n) return;
    float di = g_dinv[warp];
    float2 own = __half22float2(g_h0[warp * 32 + lane]);
    float a0 = own.x, a1 = own.y;
    int s = g_off[warp]     + __ldg(&g_bsum[warp >> 10]);
    int e = g_off[warp + 1] + __ldg(&g_bsum[(warp + 1) >> 10]);
    for (int j = s; j < e; j += 32) {
        int cnt = e - j; if (cnt > 32) cnt = 32;
        int r = (lane < cnt) ? __ldg(&g_csr_row[j + lane]) : 0;
#pragma unroll 4
        for (int t = 0; t < cnt; t++) {
            int rr = __shfl_sync(0xffffffffu, r, t);
            float2 f = __half22float2(__ldg(&g_h0[rr * 32 + lane]));
            a0 += f.x;
            a1 += f.y;
        }
    }
    float2 b = ((const float2*)bias)[lane];   // bias features (2*lane, 2*lane+1)
    a0 = fmaxf(fmaf(a0, di, b.x), 0.0f);
    a1 = fmaxf(fmaf(a1, di, b.y), 0.0f);
    g_h[warp * 32 + lane] = __floats2half2_rn(a0 * di, a1 * di);
}

// ---------------- gather2 + output heads (fused, grid-strided) ----------------
__global__ void k_g2out(const float* __restrict__ Wmu, const float* __restrict__ bmu,
                        const float* __restrict__ Wls, const float* __restrict__ bls,
                        float* __restrict__ out, int n) {
    __shared__ float Wm[F_H * F_OUT];   // 8 KB
    __shared__ float Wl[F_H * F_OUT];   // 8 KB
    int tid = threadIdx.x;
    int lane = tid & 31;
    for (int i = tid; i < F_H * F_OUT; i += 256) { Wm[i] = Wmu[i]; Wl[i] = Wls[i]; }
    __syncthreads();
    float bm = bmu[lane], bl = bls[lane];
    int gw = blockIdx.x * 8 + (tid >> 5);
    int stride = gridDim.x * 8;
    for (int node = gw; node < n; node += stride) {
        float di = g_dinv[node];
        float2 own = __half22float2(g_h[node * 32 + lane]);
        float a0 = own.x, a1 = own.y;    // features 2*lane, 2*lane+1
        int s = g_off[node]     + __ldg(&g_bsum[node >> 10]);
        int e = g_off[node + 1] + __ldg(&g_bsum[(node + 1) >> 10]);
        for (int j = s; j < e; j += 32) {
            int cnt = e - j; if (cnt > 32) cnt = 32;
            int r = (lane < cnt) ? __ldg(&g_csr_row[j + lane]) : 0;
#pragma unroll 4
            for (int t = 0; t < cnt; t++) {
                int rr = __shfl_sync(0xffffffffu, r, t);
                float2 f = __half22float2(__ldg(&g_h[rr * 32 + lane]));
                a0 += f.x;
                a1 += f.y;
            }
        }
        a0 *= di;   // g feature 2*lane
        a1 *= di;   // g feature 2*lane+1
        float mu = 0.0f, ls = 0.0f;
#pragma unroll
        for (int k = 0; k < 32; k++) {
            float gx = __shfl_sync(0xffffffffu, a0, k);   // feature 2k
            float gy = __shfl_sync(0xffffffffu, a1, k);   // feature 2k+1
            mu = fmaf(gx, Wm[(2 * k)     * F_OUT + lane], mu);
            mu = fmaf(gy, Wm[(2 * k + 1) * F_OUT + lane], mu);
            ls = fmaf(gx, Wl[(2 * k)     * F_OUT + lane], ls);
            ls = fmaf(gy, Wl[(2 * k + 1) * F_OUT + lane], ls);
        }
        out[(size_t)node * F_OUT + lane]                        = mu + bm;
        out[(size_t)n * F_OUT + (size_t)node * F_OUT + lane]    = ls + bl;
    }
}

// ---------------- launch ----------------
extern "C" void kernel_launch(void* const* d_in, const int* in_sizes, int n_in,
                              void* d_out, int out_size) {
    int n = out_size / (2 * F_OUT);

    long long best1 = -1, best2 = -1; int i1 = -1, i2 = -1;
    for (int i = 0; i < n_in; i++) {
        long long s = in_sizes[i];
        if (s > best1) { best2 = best1; i2 = i1; best1 = s; i1 = i; }
        else if (s > best2) { best2 = s; i2 = i; }
    }
    int tie = (best1 == best2);

    int idx_W1 = -1, idx_b1 = -1;
    int idx_W_a = -1, idx_W_b = -1, idx_b_a = -1, idx_b_b = -1;
    for (int i = 0; i < n_in; i++) {
        if (i == i1 || i == i2) continue;
        int s = in_sizes[i];
        if (s == F_IN * F_H) idx_W1 = i;
        else if (s == F_H) idx_b1 = i;
        else if (s == F_H * F_OUT) { if (idx_W_a < 0) idx_W_a = i; else idx_W_b = i; }
        else if (s == F_OUT) { if (idx_b_a < 0) idx_b_a = i; else idx_b_b = i; }
    }
    int min_big = (i1 < i2) ? i1 : i2;
    int mu_first = (min_big == 0) ? 1 : 0;
    int idx_Wmu = mu_first ? idx_W_a : idx_W_b;
    int idx_Wls = mu_first ? idx_W_b : idx_W_a;
    int idx_bmu = mu_first ? idx_b_a : idx_b_b;
    int idx_bls = mu_first ? idx_b_b : idx_b_a;

    int ca = (i1 < i2) ? i1 : i2;
    int cb = (i1 < i2) ? i2 : i1;
    const float* c0 = (const float*)d_in[ca];
    const float* c1 = (const float*)d_in[cb];

    int e, host_eisel = 0;
    if (tie) {
        e = in_sizes[ca] / 4;
        if (n <= 0) n = in_sizes[ca] / F_IN;
    } else {
        int idx_x  = (in_sizes[ca] > in_sizes[cb]) ? ca : cb;
        int idx_ei = (idx_x == ca) ? cb : ca;
        e = in_sizes[idx_ei] / 2;
        host_eisel = (idx_ei == cb) ? 1 : 0;
        if (n <= 0) n = in_sizes[idx_x] / F_IN;
    }
    if (n > N_NODES) n = N_NODES;
    if (e > N_EDGES) e = N_EDGES;

    const float* W1  = (const float*)d_in[idx_W1];
    const float* b1  = (const float*)d_in[idx_b1];
    const float* Wmu = (const float*)d_in[idx_Wmu];
    const float* bmu = (const float*)d_in[idx_bmu];
    const float* Wls = (const float*)d_in[idx_Wls];
    const float* bls = (const float*)d_in[idx_bls];
    float* out = (float*)d_out;

    // fork-join side stream (created once on first, non-captured, call)
    static cudaStream_t s2 = nullptr;
    static cudaEvent_t ev_fork = nullptr, ev_join = nullptr;
    if (s2 == nullptr) {
        cudaStreamCreateWithFlags(&s2, cudaStreamNonBlocking);
        cudaEventCreateWithFlags(&ev_fork, cudaEventDisableTiming);
        cudaEventCreateWithFlags(&ev_join, cudaEventDisableTiming);
    }

    int nb = (n + SCAN_BLK - 1) / SCAN_BLK;

    k_zero_probe<<<(n + 255) / 256, 256>>>((const int*)c0, (const int*)c1, tie, host_eisel, n);
    k_count     <<<(e + 255) / 256, 256>>>((const void*)c0, (const void*)c1, e, n);
    k_scan1     <<<nb, SCAN_BLK>>>(n, nb);

    // fork: gemm1 (independent of CSR fill) runs on side stream
    cudaEventRecord(ev_fork, 0);
    cudaStreamWaitEvent(s2, ev_fork, 0);
    k_gemm1<<<(n + 127) / 128, 256, 0, s2>>>(c0, c1, W1, n);
    k_fill <<<(e + 255) / 256, 256>>>((const void*)c0, (const void*)c1, e, n);
    // join
    cudaEventRecord(ev_join, s2);
    cudaStreamWaitEvent(0, ev_join, 0);

    k_gather1<<<(n + 7) / 8, 256>>>(b1, n);
    k_g2out  <<<1184, 256>>>(Wmu, bmu, Wls, bls, out, n);
}